// round 3
// baseline (speedup 1.0000x reference)
// R2: resubmission of R1 kernel — both prior rounds failed at container
// acquisition (infra), no kernel signal produced. Source unchanged.
#include <cuda_runtime.h>
#include <cstdint>

#define BATCH 2
#define NSEQ  2048
#define DIMV  1024
#define HEADS 16
#define DH    64

// Scratch (allocation-free rule: device globals)
__device__ float g_q[BATCH * HEADS * NSEQ * DH];   // [b][h][n][dh]
__device__ float g_v[BATCH * HEADS * NSEQ * DH];   // [b][h][n][dh]
__device__ float g_sq[BATCH * HEADS * NSEQ];       // ||q||^2 per (b,h,n)
__device__ float g_o[BATCH * NSEQ * DIMV];         // attention output [b][n][d]

// ---------------------------------------------------------------------------
// SGEMM (NT): C[m][n] = sum_k A[m][k] * B[n][k]
// 128x128 block tile, BK=8, 256 threads, 8x8 microtile per thread.
// mode 0: write C[m*N+n]            (if A==nullptr, A is taken from g_o)
// mode 1: scatter into g_q / g_v per-head layout (N must be 2048)
// ---------------------------------------------------------------------------
__global__ __launch_bounds__(256) void sgemm_nt(const float* __restrict__ A,
                                                const float* __restrict__ B,
                                                float* __restrict__ C,
                                                int N, int K, int mode)
{
    __shared__ float As[8][128];
    __shared__ float Bs[8][128];

    if (A == nullptr) A = g_o;

    const int tid = threadIdx.x;
    const int tx = tid & 15;        // 0..15 -> output cols tx*8..
    const int ty = tid >> 4;        // 0..15 -> output rows ty*8..
    const int lrow = tid >> 1;      // 0..127
    const int lcol = (tid & 1) * 4; // 0 or 4

    const float* Ag = A + (size_t)(blockIdx.y * 128 + lrow) * K + lcol;
    const float* Bg = B + (size_t)(blockIdx.x * 128 + lrow) * K + lcol;

    float acc[8][8];
#pragma unroll
    for (int i = 0; i < 8; i++)
#pragma unroll
        for (int j = 0; j < 8; j++) acc[i][j] = 0.0f;

    for (int k0 = 0; k0 < K; k0 += 8) {
        float4 av = *(const float4*)(Ag + k0);
        float4 bv = *(const float4*)(Bg + k0);
        As[lcol + 0][lrow] = av.x;
        As[lcol + 1][lrow] = av.y;
        As[lcol + 2][lrow] = av.z;
        As[lcol + 3][lrow] = av.w;
        Bs[lcol + 0][lrow] = bv.x;
        Bs[lcol + 1][lrow] = bv.y;
        Bs[lcol + 2][lrow] = bv.z;
        Bs[lcol + 3][lrow] = bv.w;
        __syncthreads();

#pragma unroll
        for (int kk = 0; kk < 8; kk++) {
            float a[8], b[8];
            *(float4*)(a)     = *(const float4*)&As[kk][ty * 8];
            *(float4*)(a + 4) = *(const float4*)&As[kk][ty * 8 + 4];
            *(float4*)(b)     = *(const float4*)&Bs[kk][tx * 8];
            *(float4*)(b + 4) = *(const float4*)&Bs[kk][tx * 8 + 4];
#pragma unroll
            for (int i = 0; i < 8; i++)
#pragma unroll
                for (int j = 0; j < 8; j++)
                    acc[i][j] = fmaf(a[i], b[j], acc[i][j]);
        }
        __syncthreads();
    }

    if (mode == 0) {
#pragma unroll
        for (int i = 0; i < 8; i++) {
            int m = blockIdx.y * 128 + ty * 8 + i;
#pragma unroll
            for (int j = 0; j < 8; j++) {
                int n = blockIdx.x * 128 + tx * 8 + j;
                C[(size_t)m * N + n] = acc[i][j];
            }
        }
    } else {
#pragma unroll
        for (int i = 0; i < 8; i++) {
            int m = blockIdx.y * 128 + ty * 8 + i;
            int bb = m >> 11;           // m / 2048
            int nn = m & 2047;
#pragma unroll
            for (int j = 0; j < 8; j++) {
                int e = blockIdx.x * 128 + tx * 8 + j;
                float val = acc[i][j];
                if (e < DIMV) {
                    int h = e >> 6, dd = e & 63;
                    g_q[(((size_t)(bb * HEADS + h)) * NSEQ + nn) * DH + dd] = val;
                } else {
                    int e2 = e - DIMV;
                    int h = e2 >> 6, dd = e2 & 63;
                    g_v[(((size_t)(bb * HEADS + h)) * NSEQ + nn) * DH + dd] = val;
                }
            }
        }
    }
}

// ---------------------------------------------------------------------------
// ||q||^2 per row (b,h,n): 65536 rows of 64 contiguous floats
// ---------------------------------------------------------------------------
__global__ __launch_bounds__(256) void sq_kernel()
{
    int row = blockIdx.x * blockDim.x + threadIdx.x;
    if (row >= BATCH * HEADS * NSEQ) return;
    const float4* p = reinterpret_cast<const float4*>(g_q + (size_t)row * DH);
    float s = 0.0f;
#pragma unroll
    for (int i = 0; i < 16; i++) {
        float4 v = p[i];
        s += v.x * v.x + v.y * v.y + v.z * v.z + v.w * v.w;
    }
    g_sq[row] = s;
}

// ---------------------------------------------------------------------------
// Flash-style L2 attention.
// scores row-softmax of (2*q_n.q_m - ||q_m||^2) * scale   (||q_n||^2 cancels)
// Block: 64 query rows; loop over 32 key blocks of 64.
// 256 threads (16x16); each thread 4x4 of S and 4x4 of O (dh split by tx).
// ---------------------------------------------------------------------------
#define LPAD 65
__global__ __launch_bounds__(256) void attn_kernel()
{
    extern __shared__ float sm[];
    float* Qs  = sm;                 // [64][65]
    float* Ks  = Qs + 64 * LPAD;     // [64][65]
    float* Vs  = Ks + 64 * LPAD;     // [64][65]
    float* Ps  = Vs + 64 * LPAD;     // [64][65]
    float* sqs = Ps + 64 * LPAD;     // [64]

    const int tid = threadIdx.x;
    const int tx = tid & 15;
    const int ty = tid >> 4;
    const int qb = blockIdx.x;
    const int h  = blockIdx.y;
    const int b  = blockIdx.z;

    const size_t base = ((size_t)(b * HEADS + h)) * NSEQ * DH;
    const float* Qg  = g_q + base;
    const float* Vg  = g_v + base;
    const float* sqg = g_sq + (size_t)(b * HEADS + h) * NSEQ;

    // Load Q tile [64][64]
    {
        int r  = tid >> 2;
        int c0 = (tid & 3) * 16;
        const float* src = Qg + (size_t)(qb * 64 + r) * DH + c0;
#pragma unroll
        for (int i = 0; i < 4; i++) {
            float4 v = *(const float4*)(src + i * 4);
            Qs[r * LPAD + c0 + i * 4 + 0] = v.x;
            Qs[r * LPAD + c0 + i * 4 + 1] = v.y;
            Qs[r * LPAD + c0 + i * 4 + 2] = v.z;
            Qs[r * LPAD + c0 + i * 4 + 3] = v.w;
        }
    }

    float m_i[4], l_i[4], acc[4][4];
#pragma unroll
    for (int i = 0; i < 4; i++) {
        m_i[i] = -1e30f;
        l_i[i] = 0.0f;
#pragma unroll
        for (int j = 0; j < 4; j++) acc[i][j] = 0.0f;
    }
    const float scale = 0.125f;  // dh^{-1/2} = 1/8

    for (int kb = 0; kb < NSEQ / 64; kb++) {
        // Load K, V tiles + sq
        {
            int r  = tid >> 2;
            int c0 = (tid & 3) * 16;
            const float* ksrc = Qg + (size_t)(kb * 64 + r) * DH + c0;
            const float* vsrc = Vg + (size_t)(kb * 64 + r) * DH + c0;
#pragma unroll
            for (int i = 0; i < 4; i++) {
                float4 kv = *(const float4*)(ksrc + i * 4);
                float4 vv = *(const float4*)(vsrc + i * 4);
                int c = c0 + i * 4;
                Ks[r * LPAD + c + 0] = kv.x;
                Ks[r * LPAD + c + 1] = kv.y;
                Ks[r * LPAD + c + 2] = kv.z;
                Ks[r * LPAD + c + 3] = kv.w;
                Vs[r * LPAD + c + 0] = vv.x;
                Vs[r * LPAD + c + 1] = vv.y;
                Vs[r * LPAD + c + 2] = vv.z;
                Vs[r * LPAD + c + 3] = vv.w;
            }
            if (tid < 64) sqs[tid] = sqg[kb * 64 + tid];
        }
        __syncthreads();

        // S = Q @ K^T  (4x4 per thread)
        float s[4][4];
#pragma unroll
        for (int i = 0; i < 4; i++)
#pragma unroll
            for (int j = 0; j < 4; j++) s[i][j] = 0.0f;

#pragma unroll 8
        for (int k = 0; k < 64; k++) {
            float qr[4], kr[4];
#pragma unroll
            for (int i = 0; i < 4; i++) qr[i] = Qs[(ty * 4 + i) * LPAD + k];
#pragma unroll
            for (int j = 0; j < 4; j++) kr[j] = Ks[(tx * 4 + j) * LPAD + k];
#pragma unroll
            for (int i = 0; i < 4; i++)
#pragma unroll
                for (int j = 0; j < 4; j++)
                    s[i][j] = fmaf(qr[i], kr[j], s[i][j]);
        }

        // online softmax per query row (16 threads per row share via shfl)
#pragma unroll
        for (int i = 0; i < 4; i++) {
            float rm = -1e30f;
#pragma unroll
            for (int j = 0; j < 4; j++) {
                s[i][j] = (2.0f * s[i][j] - sqs[tx * 4 + j]) * scale;
                rm = fmaxf(rm, s[i][j]);
            }
#pragma unroll
            for (int o = 8; o > 0; o >>= 1)
                rm = fmaxf(rm, __shfl_xor_sync(0xffffffffu, rm, o, 16));
            float mnew = fmaxf(m_i[i], rm);
            float corr = __expf(m_i[i] - mnew);
            m_i[i] = mnew;
            float ps = 0.0f;
#pragma unroll
            for (int j = 0; j < 4; j++) {
                float p = __expf(s[i][j] - mnew);
                Ps[(ty * 4 + i) * LPAD + tx * 4 + j] = p;
                ps += p;
            }
#pragma unroll
            for (int o = 8; o > 0; o >>= 1)
                ps += __shfl_xor_sync(0xffffffffu, ps, o, 16);
            l_i[i] = l_i[i] * corr + ps;
#pragma unroll
            for (int j = 0; j < 4; j++) acc[i][j] *= corr;
        }
        __syncthreads();

        // O += P @ V
#pragma unroll 8
        for (int k = 0; k < 64; k++) {
            float pr[4], vr[4];
#pragma unroll
            for (int i = 0; i < 4; i++) pr[i] = Ps[(ty * 4 + i) * LPAD + k];
#pragma unroll
            for (int j = 0; j < 4; j++) vr[j] = Vs[k * LPAD + tx * 4 + j];
#pragma unroll
            for (int i = 0; i < 4; i++)
#pragma unroll
                for (int j = 0; j < 4; j++)
                    acc[i][j] = fmaf(pr[i], vr[j], acc[i][j]);
        }
        __syncthreads();
    }

    // Normalize and write to g_o[b][n][h*64+dh]
#pragma unroll
    for (int i = 0; i < 4; i++) {
        int n = qb * 64 + ty * 4 + i;
        float inv = 1.0f / l_i[i];
#pragma unroll
        for (int j = 0; j < 4; j++) {
            int d = h * DH + tx * 4 + j;
            g_o[((size_t)b * NSEQ + n) * DIMV + d] = acc[i][j] * inv;
        }
    }
}

// ---------------------------------------------------------------------------

extern "C" void kernel_launch(void* const* d_in, const int* in_sizes, int n_in,
                              void* d_out, int out_size)
{
    const float* x    = (const float*)d_in[0];   // [2,2048,1024]
    const float* w_qv = (const float*)d_in[1];   // [2048,1024]
    const float* w_o  = (const float*)d_in[2];   // [1024,1024]
    float* out = (float*)d_out;                  // [2,2048,1024]

    const int smem_attn = (4 * 64 * LPAD + 64) * (int)sizeof(float);  // ~66.8 KB
    cudaFuncSetAttribute(attn_kernel, cudaFuncAttributeMaxDynamicSharedMemorySize,
                         smem_attn);

    // 1) QV projection: M=4096, N=2048, K=1024, scatter epilogue
    sgemm_nt<<<dim3(2048 / 128, 4096 / 128), 256>>>(x, w_qv, nullptr, 2048, 1024, 1);

    // 2) ||q||^2
    sq_kernel<<<(BATCH * HEADS * NSEQ) / 256, 256>>>();

    // 3) flash L2 attention
    attn_kernel<<<dim3(NSEQ / 64, HEADS, BATCH), 256, smem_attn>>>();

    // 4) output projection: M=4096, N=1024, K=1024 (A = g_o via nullptr)
    sgemm_nt<<<dim3(1024 / 128, 4096 / 128), 256>>>(nullptr, w_o, out,
                                                    1024, 1024, 0);
}

// round 8
// speedup vs baseline: 1.2673x; 1.2673x over previous
// R7: fix 128MiB mem-delta: it tracked the STATIC DEVICE GLOBALS (92MB in
//     R4-R6, slab rounds to 128MiB at lazy module load during correctness
//     run), not kernel spills. Globals cut to 56.25MB via buffer aliasing;
//     all device-buffer selection moved on-device (no host symbol passing).
#include <cuda_runtime.h>
#include <cuda_bf16.h>
#include <cstdint>

#define BATCH 2
#define NSEQ  2048
#define DIMV  1024
#define HEADS 16
#define DH    64

// ---------------- scratch (device globals; total 56.25 MB) ------------------
__device__ float g_q[BATCH * HEADS * NSEQ * DH];    // 16 MB
__device__ float g_v[BATCH * HEADS * NSEQ * DH];    // 16 MB
__device__ float g_sq[BATCH * HEADS * NSEQ];        // 0.25 MB
// A-side split pair: x (hi/lo) during QV gemm, attention-output (hi/lo)
// during Wo gemm. 8 MB each.
__device__ __nv_bfloat16 g_ahi[4096 * 1024];
__device__ __nv_bfloat16 g_alo[4096 * 1024];
// B-side split pair: w_qv during QV gemm, then overwritten with w_o. 4 MB each.
__device__ __nv_bfloat16 g_bhi[2048 * 1024];
__device__ __nv_bfloat16 g_blo[2048 * 1024];

// ---------------- helpers ---------------------------------------------------
__device__ __forceinline__ uint32_t smem_u32(const void* p) {
    uint32_t a;
    asm("{ .reg .u64 t; cvta.to.shared.u64 t, %1; cvt.u32.u64 %0, t; }"
        : "=r"(a) : "l"(p));
    return a;
}
#define LDSM_X4(r0, r1, r2, r3, addr)                                        \
    asm volatile("ldmatrix.sync.aligned.m8n8.x4.shared.b16 {%0,%1,%2,%3}, [%4];" \
                 : "=r"(r0), "=r"(r1), "=r"(r2), "=r"(r3) : "r"(addr))
#define MMA16816(d, a, b0, b1)                                               \
    asm volatile("mma.sync.aligned.m16n8k16.row.col.f32.bf16.bf16.f32 "      \
                 "{%0,%1,%2,%3}, {%4,%5,%6,%7}, {%8,%9}, {%0,%1,%2,%3};"     \
                 : "+f"((d)[0]), "+f"((d)[1]), "+f"((d)[2]), "+f"((d)[3])    \
                 : "r"((a)[0]), "r"((a)[1]), "r"((a)[2]), "r"((a)[3]),       \
                   "r"(b0), "r"(b1))
#define CP_ASYNC16(dst, src)                                                 \
    asm volatile("cp.async.cg.shared.global [%0], [%1], 16;"                 \
                 :: "r"(dst), "l"(src))
#define CP_COMMIT() asm volatile("cp.async.commit_group;" ::: "memory")
#define CP_WAIT(n)  asm volatile("cp.async.wait_group %0;" :: "n"(n) : "memory")

union BU { __nv_bfloat162 b; uint32_t u; };
__device__ __forceinline__ uint32_t pack_hi2(float x, float y) {
    BU t; t.b = __floats2bfloat162_rn(x, y); return t.u;
}
__device__ __forceinline__ uint32_t pack_lo2(float x, float y) {
    float rx = x - __bfloat162float(__float2bfloat16(x));
    float ry = y - __bfloat162float(__float2bfloat16(y));
    BU t; t.b = __floats2bfloat162_rn(rx, ry); return t.u;
}

// ---------------------------------------------------------------------------
// split fp32 -> bf16 hi + lo. which=0 -> (g_ahi,g_alo); which=1 -> (g_bhi,g_blo)
// ---------------------------------------------------------------------------
__global__ __launch_bounds__(256) void split_kernel(const float* __restrict__ src,
                                                    int which, int n)
{
    int i = (blockIdx.x * 256 + threadIdx.x) * 8;
    if (i >= n) return;
    __nv_bfloat16* hi = which ? g_bhi : g_ahi;
    __nv_bfloat16* lo = which ? g_blo : g_alo;
    float4 a = *(const float4*)(src + i);
    float4 b = *(const float4*)(src + i + 4);
    uint4 hv, lv;
    hv.x = pack_hi2(a.x, a.y);  hv.y = pack_hi2(a.z, a.w);
    hv.z = pack_hi2(b.x, b.y);  hv.w = pack_hi2(b.z, b.w);
    lv.x = pack_lo2(a.x, a.y);  lv.y = pack_lo2(a.z, a.w);
    lv.z = pack_lo2(b.x, b.y);  lv.w = pack_lo2(b.z, b.w);
    *(uint4*)(hi + i) = hv;
    *(uint4*)(lo + i) = lv;
}

// ---------------------------------------------------------------------------
// mma.sync bf16x3 GEMM (NT): C = A[M x 1024] * B[N x 1024]^T, fp32 acc.
// A = (g_ahi, g_alo), B = (g_bhi, g_blo) -- always the internal pairs.
// Block 128x128, BK=32, 8 warps (64x32 each), cp.async 2-stage pipeline.
// mode 0: C[m*ldc+n] = acc.  mode 1: scatter into g_q/g_v head layout.
// ---------------------------------------------------------------------------
#define KDIM   1024
#define SROW   40                      // bf16/row: 80B stride, LDSM conflict-free
#define ABYTES (128 * SROW * 2)        // 10240 B per operand tile
#define STAGEB (4 * ABYTES)            // 40960 B per stage
#define GEMM_SMEM (2 * STAGEB)         // 81920 B

__global__ __launch_bounds__(256, 1) void mma_gemm(float* __restrict__ C,
                                                   int ldc, int mode)
{
    extern __shared__ char smem[];
    const uint32_t sbase = smem_u32(smem);

    const int tid  = threadIdx.x;
    const int warp = tid >> 5;
    const int lane = tid & 31;
    const int wm   = warp & 1;
    const int wn   = warp >> 1;

    const int m0 = blockIdx.y * 128;
    const int n0 = blockIdx.x * 128;

    const int lrow  = tid >> 1;
    const int lhalf = (tid & 1) * 16;
    const __nv_bfloat16* pAh = g_ahi + (size_t)(m0 + lrow) * KDIM + lhalf;
    const __nv_bfloat16* pAl = g_alo + (size_t)(m0 + lrow) * KDIM + lhalf;
    const __nv_bfloat16* pBh = g_bhi + (size_t)(n0 + lrow) * KDIM + lhalf;
    const __nv_bfloat16* pBl = g_blo + (size_t)(n0 + lrow) * KDIM + lhalf;
    const uint32_t so = (uint32_t)(lrow * SROW + lhalf) * 2;

    const int fr = (lane & 7) + ((lane >> 3) & 1) * 8;
    const int fc = (lane >> 4) * 8;

    float acc[4][4][4];
#pragma unroll
    for (int i = 0; i < 4; i++)
#pragma unroll
        for (int j = 0; j < 4; j++)
#pragma unroll
            for (int c = 0; c < 4; c++) acc[i][j][c] = 0.0f;

#define ISSUE(ch) do {                                                       \
        const uint32_t st = sbase + ((ch) & 1) * STAGEB + so;                \
        const int ko = (ch) * 32;                                            \
        CP_ASYNC16(st,                  pAh + ko);                           \
        CP_ASYNC16(st + 16,             pAh + ko + 8);                       \
        CP_ASYNC16(st + ABYTES,         pAl + ko);                           \
        CP_ASYNC16(st + ABYTES + 16,    pAl + ko + 8);                       \
        CP_ASYNC16(st + 2 * ABYTES,      pBh + ko);                          \
        CP_ASYNC16(st + 2 * ABYTES + 16, pBh + ko + 8);                      \
        CP_ASYNC16(st + 3 * ABYTES,      pBl + ko);                          \
        CP_ASYNC16(st + 3 * ABYTES + 16, pBl + ko + 8);                      \
        CP_COMMIT();                                                         \
    } while (0)

    ISSUE(0);

    for (int ch = 0; ch < KDIM / 32; ch++) {
        if (ch + 1 < KDIM / 32) { ISSUE(ch + 1); CP_WAIT(1); }
        else                    { CP_WAIT(0); }
        __syncthreads();

        const char* stg = smem + (ch & 1) * STAGEB;
        const __nv_bfloat16* sAh = (const __nv_bfloat16*)(stg);
        const __nv_bfloat16* sAl = (const __nv_bfloat16*)(stg + ABYTES);
        const __nv_bfloat16* sBh = (const __nv_bfloat16*)(stg + 2 * ABYTES);
        const __nv_bfloat16* sBl = (const __nv_bfloat16*)(stg + 3 * ABYTES);

#pragma unroll
        for (int ks = 0; ks < 2; ks++) {
            const int kc = ks * 16 + fc;
            uint32_t bh[2][4], bl[2][4];
#pragma unroll
            for (int np = 0; np < 2; np++) {
                const int row = wn * 32 + np * 16 + fr;
                LDSM_X4(bh[np][0], bh[np][1], bh[np][2], bh[np][3],
                        smem_u32(sBh + row * SROW + kc));
                LDSM_X4(bl[np][0], bl[np][1], bl[np][2], bl[np][3],
                        smem_u32(sBl + row * SROW + kc));
            }
#pragma unroll
            for (int mt = 0; mt < 4; mt++) {
                const int row = wm * 64 + mt * 16 + fr;
                uint32_t ah[4], al[4];
                LDSM_X4(ah[0], ah[1], ah[2], ah[3],
                        smem_u32(sAh + row * SROW + kc));
                LDSM_X4(al[0], al[1], al[2], al[3],
                        smem_u32(sAl + row * SROW + kc));
#pragma unroll
                for (int nt = 0; nt < 4; nt++) {
                    const int np = nt >> 1, sub = nt & 1;
                    const uint32_t b0h = bh[np][sub], b1h = bh[np][sub + 2];
                    const uint32_t b0l = bl[np][sub], b1l = bl[np][sub + 2];
                    MMA16816(acc[mt][nt], ah, b0h, b1h);
                    MMA16816(acc[mt][nt], ah, b0l, b1l);
                    MMA16816(acc[mt][nt], al, b0h, b1h);
                }
            }
        }
        __syncthreads();
    }

    const int r0 = lane >> 2;
    const int c0 = (lane & 3) * 2;
#pragma unroll
    for (int mt = 0; mt < 4; mt++) {
#pragma unroll
        for (int half = 0; half < 2; half++) {
            const int m = m0 + wm * 64 + mt * 16 + r0 + half * 8;
#pragma unroll
            for (int nt = 0; nt < 4; nt++) {
                const int e = n0 + wn * 32 + nt * 8 + c0;
                float2 v;
                v.x = acc[mt][nt][half * 2 + 0];
                v.y = acc[mt][nt][half * 2 + 1];
                if (mode == 0) {
                    *(float2*)(C + (size_t)m * ldc + e) = v;
                } else {
                    const int bb = m >> 11, nn = m & 2047;
                    float* dst;
                    if (e < DIMV) {
                        const int h = e >> 6, d0 = e & 63;
                        dst = g_q + (((size_t)(bb * HEADS + h)) * NSEQ + nn) * DH + d0;
                    } else {
                        const int e2 = e - DIMV;
                        const int h = e2 >> 6, d0 = e2 & 63;
                        dst = g_v + (((size_t)(bb * HEADS + h)) * NSEQ + nn) * DH + d0;
                    }
                    *(float2*)dst = v;
                }
            }
        }
    }
}

// ---------------------------------------------------------------------------
// ||q||^2 per row
// ---------------------------------------------------------------------------
__global__ __launch_bounds__(256) void sq_kernel()
{
    int row = blockIdx.x * blockDim.x + threadIdx.x;
    if (row >= BATCH * HEADS * NSEQ) return;
    const float4* p = reinterpret_cast<const float4*>(g_q + (size_t)row * DH);
    float s = 0.0f;
#pragma unroll
    for (int i = 0; i < 16; i++) {
        float4 v = p[i];
        s += v.x * v.x + v.y * v.y + v.z * v.z + v.w * v.w;
    }
    g_sq[row] = s;
}

// ---------------------------------------------------------------------------
// L2 attention, analytic row max (=0 at m=n):
//   p = exp((2 q.k - sq_m)*scale - sq_n*scale), no online softmax.
// Output written directly as bf16 hi/lo split into g_ahi/g_alo (A of Wo gemm).
// ---------------------------------------------------------------------------
#define LPAD 65
__global__ __launch_bounds__(256) void attn_kernel()
{
    extern __shared__ float sm[];
    float* Qs  = sm;
    float* Ks  = Qs + 64 * LPAD;
    float* Vs  = Ks + 64 * LPAD;
    float* Ps  = Vs + 64 * LPAD;
    float* sqs = Ps + 64 * LPAD;

    const int tid = threadIdx.x;
    const int tx = tid & 15;
    const int ty = tid >> 4;
    const int qb = blockIdx.x;
    const int h  = blockIdx.y;
    const int b  = blockIdx.z;

    const size_t base = ((size_t)(b * HEADS + h)) * NSEQ * DH;
    const float* Qg  = g_q + base;
    const float* Vg  = g_v + base;
    const float* sqg = g_sq + (size_t)(b * HEADS + h) * NSEQ;

    {
        int r  = tid >> 2;
        int c0 = (tid & 3) * 16;
        const float* src = Qg + (size_t)(qb * 64 + r) * DH + c0;
#pragma unroll
        for (int i = 0; i < 4; i++) {
            float4 v = *(const float4*)(src + i * 4);
            Qs[r * LPAD + c0 + i * 4 + 0] = v.x;
            Qs[r * LPAD + c0 + i * 4 + 1] = v.y;
            Qs[r * LPAD + c0 + i * 4 + 2] = v.z;
            Qs[r * LPAD + c0 + i * 4 + 3] = v.w;
        }
    }

    const float scale = 0.125f;
    float sqn[4], l_i[4], acc[4][4];
#pragma unroll
    for (int i = 0; i < 4; i++) {
        sqn[i] = sqg[qb * 64 + ty * 4 + i] * scale;
        l_i[i] = 0.0f;
#pragma unroll
        for (int j = 0; j < 4; j++) acc[i][j] = 0.0f;
    }

    for (int kb = 0; kb < NSEQ / 64; kb++) {
        {
            int r  = tid >> 2;
            int c0 = (tid & 3) * 16;
            const float* ksrc = Qg + (size_t)(kb * 64 + r) * DH + c0;
            const float* vsrc = Vg + (size_t)(kb * 64 + r) * DH + c0;
#pragma unroll
            for (int i = 0; i < 4; i++) {
                float4 kv = *(const float4*)(ksrc + i * 4);
                float4 vv = *(const float4*)(vsrc + i * 4);
                int c = c0 + i * 4;
                Ks[r * LPAD + c + 0] = kv.x;
                Ks[r * LPAD + c + 1] = kv.y;
                Ks[r * LPAD + c + 2] = kv.z;
                Ks[r * LPAD + c + 3] = kv.w;
                Vs[r * LPAD + c + 0] = vv.x;
                Vs[r * LPAD + c + 1] = vv.y;
                Vs[r * LPAD + c + 2] = vv.z;
                Vs[r * LPAD + c + 3] = vv.w;
            }
            if (tid < 64) sqs[tid] = sqg[kb * 64 + tid];
        }
        __syncthreads();

        float s[4][4];
#pragma unroll
        for (int i = 0; i < 4; i++)
#pragma unroll
            for (int j = 0; j < 4; j++) s[i][j] = 0.0f;

#pragma unroll 8
        for (int k = 0; k < 64; k++) {
            float qr[4], kr[4];
#pragma unroll
            for (int i = 0; i < 4; i++) qr[i] = Qs[(ty * 4 + i) * LPAD + k];
#pragma unroll
            for (int j = 0; j < 4; j++) kr[j] = Ks[(tx * 4 + j) * LPAD + k];
#pragma unroll
            for (int i = 0; i < 4; i++)
#pragma unroll
                for (int j = 0; j < 4; j++)
                    s[i][j] = fmaf(qr[i], kr[j], s[i][j]);
        }

#pragma unroll
        for (int i = 0; i < 4; i++) {
#pragma unroll
            for (int j = 0; j < 4; j++) {
                float p = __expf(fmaf(2.0f * s[i][j] - sqs[tx * 4 + j], scale, -sqn[i]));
                Ps[(ty * 4 + i) * LPAD + tx * 4 + j] = p;
                l_i[i] += p;
            }
        }
        __syncthreads();

#pragma unroll 8
        for (int k = 0; k < 64; k++) {
            float pr[4], vr[4];
#pragma unroll
            for (int i = 0; i < 4; i++) pr[i] = Ps[(ty * 4 + i) * LPAD + k];
#pragma unroll
            for (int j = 0; j < 4; j++) vr[j] = Vs[k * LPAD + tx * 4 + j];
#pragma unroll
            for (int i = 0; i < 4; i++)
#pragma unroll
                for (int j = 0; j < 4; j++)
                    acc[i][j] = fmaf(pr[i], vr[j], acc[i][j]);
        }
        __syncthreads();
    }

    // final row-sum across 16 tx lanes, then write bf16 hi/lo split output
#pragma unroll
    for (int i = 0; i < 4; i++) {
        float l = l_i[i];
#pragma unroll
        for (int o = 8; o > 0; o >>= 1)
            l += __shfl_xor_sync(0xffffffffu, l, o, 16);
        float inv = 1.0f / l;
        int n = qb * 64 + ty * 4 + i;
        size_t idx = ((size_t)b * NSEQ + n) * DIMV + h * DH + tx * 4;
        float v0 = acc[i][0] * inv, v1 = acc[i][1] * inv;
        float v2 = acc[i][2] * inv, v3 = acc[i][3] * inv;
        *(uint32_t*)(g_ahi + idx)     = pack_hi2(v0, v1);
        *(uint32_t*)(g_ahi + idx + 2) = pack_hi2(v2, v3);
        *(uint32_t*)(g_alo + idx)     = pack_lo2(v0, v1);
        *(uint32_t*)(g_alo + idx + 2) = pack_lo2(v2, v3);
    }
}

// ---------------------------------------------------------------------------

extern "C" void kernel_launch(void* const* d_in, const int* in_sizes, int n_in,
                              void* d_out, int out_size)
{
    const float* x    = (const float*)d_in[0];   // [2,2048,1024]
    const float* w_qv = (const float*)d_in[1];   // [2048,1024]
    const float* w_o  = (const float*)d_in[2];   // [1024,1024]
    float* out = (float*)d_out;                  // [2,2048,1024]

    const int smem_attn = (4 * 64 * LPAD + 64) * (int)sizeof(float);
    cudaFuncSetAttribute(attn_kernel, cudaFuncAttributeMaxDynamicSharedMemorySize,
                         smem_attn);
    cudaFuncSetAttribute(mma_gemm, cudaFuncAttributeMaxDynamicSharedMemorySize,
                         GEMM_SMEM);

    // 1) split x -> A pair, w_qv -> B pair
    split_kernel<<<4096 * 1024 / 8 / 256, 256>>>(x, 0, 4096 * 1024);
    split_kernel<<<2048 * 1024 / 8 / 256, 256>>>(w_qv, 1, 2048 * 1024);

    // 2) QV projection: M=4096, N=2048, scatter into g_q/g_v
    mma_gemm<<<dim3(16, 32), 256, GEMM_SMEM>>>(nullptr, 0, 1);

    // 3) split w_o -> B pair (overwrites wqv split; stream-ordered after QV)
    split_kernel<<<1024 * 1024 / 8 / 256, 256>>>(w_o, 1, 1024 * 1024);

    // 4) ||q||^2
    sq_kernel<<<(BATCH * HEADS * NSEQ) / 256, 256>>>();

    // 5) attention -> writes bf16 hi/lo output into A pair
    attn_kernel<<<dim3(NSEQ / 64, HEADS, BATCH), 256, smem_attn>>>();

    // 6) Wo projection: M=4096, N=1024 -> out
    mma_gemm<<<dim3(8, 32), 256, GEMM_SMEM>>>(out, 1024, 0);
}

// round 11
// speedup vs baseline: 2.4750x; 1.9531x over previous
// R10: verbatim resubmission of R8/R9 — rounds 9 and 10 both died at GB300
//      container acquisition (infra); the kernel has never been compiled or
//      run. No source changes; see R9 header for the static audit summary.
#include <cuda_runtime.h>
#include <cuda_bf16.h>
#include <cstdint>

#define BATCH 2
#define NSEQ  2048
#define DIMV  1024
#define HEADS 16
#define DH    64

// ---------------- scratch (device globals; total 56.25 MB) ------------------
__device__ float g_sq[BATCH * HEADS * NSEQ];                    // 0.25 MB
__device__ __nv_bfloat16 g_qhi[BATCH * HEADS * NSEQ * DH];      // 8 MB  [bh][n][d]
__device__ __nv_bfloat16 g_qlo[BATCH * HEADS * NSEQ * DH];      // 8 MB
__device__ __nv_bfloat16 g_vhi[BATCH * HEADS * DH * NSEQ];      // 8 MB  [bh][d][n]
__device__ __nv_bfloat16 g_vlo[BATCH * HEADS * DH * NSEQ];      // 8 MB
__device__ __nv_bfloat16 g_ahi[4096 * 1024];                    // 8 MB  gemm A
__device__ __nv_bfloat16 g_alo[4096 * 1024];                    // 8 MB
__device__ __nv_bfloat16 g_bhi[2048 * 1024];                    // 4 MB  gemm B
__device__ __nv_bfloat16 g_blo[2048 * 1024];                    // 4 MB

// ---------------- helpers ---------------------------------------------------
__device__ __forceinline__ uint32_t smem_u32(const void* p) {
    uint32_t a;
    asm("{ .reg .u64 t; cvta.to.shared.u64 t, %1; cvt.u32.u64 %0, t; }"
        : "=r"(a) : "l"(p));
    return a;
}
#define LDSM_X4(r0, r1, r2, r3, addr)                                        \
    asm volatile("ldmatrix.sync.aligned.m8n8.x4.shared.b16 {%0,%1,%2,%3}, [%4];" \
                 : "=r"(r0), "=r"(r1), "=r"(r2), "=r"(r3) : "r"(addr))
#define MMA16816(d, a, b0, b1)                                               \
    asm volatile("mma.sync.aligned.m16n8k16.row.col.f32.bf16.bf16.f32 "      \
                 "{%0,%1,%2,%3}, {%4,%5,%6,%7}, {%8,%9}, {%0,%1,%2,%3};"     \
                 : "+f"((d)[0]), "+f"((d)[1]), "+f"((d)[2]), "+f"((d)[3])    \
                 : "r"((a)[0]), "r"((a)[1]), "r"((a)[2]), "r"((a)[3]),       \
                   "r"(b0), "r"(b1))
#define CP_ASYNC16(dst, src)                                                 \
    asm volatile("cp.async.cg.shared.global [%0], [%1], 16;"                 \
                 :: "r"(dst), "l"(src))
#define CP_COMMIT() asm volatile("cp.async.commit_group;" ::: "memory")
#define CP_WAIT(n)  asm volatile("cp.async.wait_group %0;" :: "n"(n) : "memory")
#define STS32(addr, v)                                                       \
    asm volatile("st.shared.u32 [%0], %1;" :: "r"(addr), "r"(v) : "memory")

union BU { __nv_bfloat162 b; uint32_t u; };
__device__ __forceinline__ uint32_t pack_hi2(float x, float y) {
    BU t; t.b = __floats2bfloat162_rn(x, y); return t.u;
}
__device__ __forceinline__ uint32_t pack_lo2(float x, float y) {
    float rx = x - __bfloat162float(__float2bfloat16(x));
    float ry = y - __bfloat162float(__float2bfloat16(y));
    BU t; t.b = __floats2bfloat162_rn(rx, ry); return t.u;
}
__device__ __forceinline__ float ex2(float x) {
    float y; asm("ex2.approx.ftz.f32 %0, %1;" : "=f"(y) : "f"(x)); return y;
}

// ---------------------------------------------------------------------------
// split fp32 -> bf16 hi + lo. which=0 -> (g_ahi,g_alo); which=1 -> (g_bhi,g_blo)
// ---------------------------------------------------------------------------
__global__ __launch_bounds__(256) void split_kernel(const float* __restrict__ src,
                                                    int which, int n)
{
    int i = (blockIdx.x * 256 + threadIdx.x) * 8;
    if (i >= n) return;
    __nv_bfloat16* hi = which ? g_bhi : g_ahi;
    __nv_bfloat16* lo = which ? g_blo : g_alo;
    float4 a = *(const float4*)(src + i);
    float4 b = *(const float4*)(src + i + 4);
    uint4 hv, lv;
    hv.x = pack_hi2(a.x, a.y);  hv.y = pack_hi2(a.z, a.w);
    hv.z = pack_hi2(b.x, b.y);  hv.w = pack_hi2(b.z, b.w);
    lv.x = pack_lo2(a.x, a.y);  lv.y = pack_lo2(a.z, a.w);
    lv.z = pack_lo2(b.x, b.y);  lv.w = pack_lo2(b.z, b.w);
    *(uint4*)(hi + i) = hv;
    *(uint4*)(lo + i) = lv;
}

// ---------------------------------------------------------------------------
// mma.sync bf16x3 GEMM (NT). mode 0: C[m*ldc+n]. mode 1: scatter q/v splits.
// ---------------------------------------------------------------------------
#define KDIM   1024
#define SROW   40
#define ABYTES (128 * SROW * 2)
#define STAGEB (4 * ABYTES)
#define GEMM_SMEM (2 * STAGEB)

__global__ __launch_bounds__(256, 1) void mma_gemm(float* __restrict__ C,
                                                   int ldc, int mode)
{
    extern __shared__ char smem[];
    const uint32_t sbase = smem_u32(smem);

    const int tid  = threadIdx.x;
    const int warp = tid >> 5;
    const int lane = tid & 31;
    const int wm   = warp & 1;
    const int wn   = warp >> 1;

    const int m0 = blockIdx.y * 128;
    const int n0 = blockIdx.x * 128;

    const int lrow  = tid >> 1;
    const int lhalf = (tid & 1) * 16;
    const __nv_bfloat16* pAh = g_ahi + (size_t)(m0 + lrow) * KDIM + lhalf;
    const __nv_bfloat16* pAl = g_alo + (size_t)(m0 + lrow) * KDIM + lhalf;
    const __nv_bfloat16* pBh = g_bhi + (size_t)(n0 + lrow) * KDIM + lhalf;
    const __nv_bfloat16* pBl = g_blo + (size_t)(n0 + lrow) * KDIM + lhalf;
    const uint32_t so = (uint32_t)(lrow * SROW + lhalf) * 2;

    const int fr = (lane & 7) + ((lane >> 3) & 1) * 8;
    const int fc = (lane >> 4) * 8;

    float acc[4][4][4];
#pragma unroll
    for (int i = 0; i < 4; i++)
#pragma unroll
        for (int j = 0; j < 4; j++)
#pragma unroll
            for (int c = 0; c < 4; c++) acc[i][j][c] = 0.0f;

#define ISSUE(ch) do {                                                       \
        const uint32_t st = sbase + ((ch) & 1) * STAGEB + so;                \
        const int ko = (ch) * 32;                                            \
        CP_ASYNC16(st,                  pAh + ko);                           \
        CP_ASYNC16(st + 16,             pAh + ko + 8);                       \
        CP_ASYNC16(st + ABYTES,         pAl + ko);                           \
        CP_ASYNC16(st + ABYTES + 16,    pAl + ko + 8);                       \
        CP_ASYNC16(st + 2 * ABYTES,      pBh + ko);                          \
        CP_ASYNC16(st + 2 * ABYTES + 16, pBh + ko + 8);                      \
        CP_ASYNC16(st + 3 * ABYTES,      pBl + ko);                          \
        CP_ASYNC16(st + 3 * ABYTES + 16, pBl + ko + 8);                      \
        CP_COMMIT();                                                         \
    } while (0)

    ISSUE(0);

    for (int ch = 0; ch < KDIM / 32; ch++) {
        if (ch + 1 < KDIM / 32) { ISSUE(ch + 1); CP_WAIT(1); }
        else                    { CP_WAIT(0); }
        __syncthreads();

        const char* stg = smem + (ch & 1) * STAGEB;
        const __nv_bfloat16* sAh = (const __nv_bfloat16*)(stg);
        const __nv_bfloat16* sAl = (const __nv_bfloat16*)(stg + ABYTES);
        const __nv_bfloat16* sBh = (const __nv_bfloat16*)(stg + 2 * ABYTES);
        const __nv_bfloat16* sBl = (const __nv_bfloat16*)(stg + 3 * ABYTES);

#pragma unroll
        for (int ks = 0; ks < 2; ks++) {
            const int kc = ks * 16 + fc;
            uint32_t bh[2][4], bl[2][4];
#pragma unroll
            for (int np = 0; np < 2; np++) {
                const int row = wn * 32 + np * 16 + fr;
                LDSM_X4(bh[np][0], bh[np][1], bh[np][2], bh[np][3],
                        smem_u32(sBh + row * SROW + kc));
                LDSM_X4(bl[np][0], bl[np][1], bl[np][2], bl[np][3],
                        smem_u32(sBl + row * SROW + kc));
            }
#pragma unroll
            for (int mt = 0; mt < 4; mt++) {
                const int row = wm * 64 + mt * 16 + fr;
                uint32_t ah[4], al[4];
                LDSM_X4(ah[0], ah[1], ah[2], ah[3],
                        smem_u32(sAh + row * SROW + kc));
                LDSM_X4(al[0], al[1], al[2], al[3],
                        smem_u32(sAl + row * SROW + kc));
#pragma unroll
                for (int nt = 0; nt < 4; nt++) {
                    const int np = nt >> 1, sub = nt & 1;
                    const uint32_t b0h = bh[np][sub], b1h = bh[np][sub + 2];
                    const uint32_t b0l = bl[np][sub], b1l = bl[np][sub + 2];
                    MMA16816(acc[mt][nt], ah, b0h, b1h);
                    MMA16816(acc[mt][nt], ah, b0l, b1l);
                    MMA16816(acc[mt][nt], al, b0h, b1h);
                }
            }
        }
        __syncthreads();
    }

    const int r0 = lane >> 2;
    const int c0 = (lane & 3) * 2;
#pragma unroll
    for (int mt = 0; mt < 4; mt++) {
#pragma unroll
        for (int half = 0; half < 2; half++) {
            const int m = m0 + wm * 64 + mt * 16 + r0 + half * 8;
#pragma unroll
            for (int nt = 0; nt < 4; nt++) {
                const int e = n0 + wn * 32 + nt * 8 + c0;
                float vx = acc[mt][nt][half * 2 + 0];
                float vy = acc[mt][nt][half * 2 + 1];
                if (mode == 0) {
                    float2 v; v.x = vx; v.y = vy;
                    *(float2*)(C + (size_t)m * ldc + e) = v;
                } else {
                    const int bb = m >> 11, nn = m & 2047;
                    if (e < DIMV) {
                        const int hh = e >> 6, d0 = e & 63;
                        size_t idx = (((size_t)(bb * HEADS + hh)) * NSEQ + nn) * DH + d0;
                        *(uint32_t*)(g_qhi + idx) = pack_hi2(vx, vy);
                        *(uint32_t*)(g_qlo + idx) = pack_lo2(vx, vy);
                    } else {
                        const int e2 = e - DIMV;
                        const int hh = e2 >> 6, d0 = e2 & 63;
                        size_t bs = ((size_t)(bb * HEADS + hh)) * DH;
                        __nv_bfloat16 hx = __float2bfloat16(vx);
                        __nv_bfloat16 hy = __float2bfloat16(vy);
                        g_vhi[(bs + d0)     * NSEQ + nn] = hx;
                        g_vhi[(bs + d0 + 1) * NSEQ + nn] = hy;
                        g_vlo[(bs + d0)     * NSEQ + nn] =
                            __float2bfloat16(vx - __bfloat162float(hx));
                        g_vlo[(bs + d0 + 1) * NSEQ + nn] =
                            __float2bfloat16(vy - __bfloat162float(hy));
                    }
                }
            }
        }
    }
}

// ---------------------------------------------------------------------------
// ||q||^2 per row from the split representation (consistent with QK mma)
// ---------------------------------------------------------------------------
__global__ __launch_bounds__(256) void sq_kernel()
{
    int row = blockIdx.x * blockDim.x + threadIdx.x;
    if (row >= BATCH * HEADS * NSEQ) return;
    const uint32_t* ph = (const uint32_t*)(g_qhi + (size_t)row * DH);
    const uint32_t* pl = (const uint32_t*)(g_qlo + (size_t)row * DH);
    float s = 0.0f;
#pragma unroll
    for (int i = 0; i < 32; i++) {
        BU uh; uh.u = ph[i];
        BU ul; ul.u = pl[i];
        float2 fh = __bfloat1622float2(uh.b);
        float2 fl = __bfloat1622float2(ul.b);
        float x = fh.x + fl.x, y = fh.y + fl.y;
        s += x * x + y * y;
    }
    g_sq[row] = s;
}

// ---------------------------------------------------------------------------
// mma.sync split-bf16 L2 attention. 128 q-rows/CTA, K/V tiles of 64 keys.
// score max = 0 analytically; p = exp2((2s - sqm)*C - sqn*C), C = log2e/8.
// Output written as bf16 hi/lo split into g_ahi/g_alo (A of Wo gemm).
// ---------------------------------------------------------------------------
#define A_SQH  0
#define A_SQL  18432
#define A_ST0  36864
#define A_STSZ 37376
#define A_KH   0
#define A_KL   9216
#define A_VH   18432
#define A_VL   27648
#define A_SQS  36864
#define A_PH   111616
#define A_PL   130048
#define A_L2D  148480
#define ATT_SMEM 149504

__global__ __launch_bounds__(256, 1) void mma_attn()
{
    extern __shared__ char sm[];
    const uint32_t sb = smem_u32(sm);
    const int tid  = threadIdx.x;
    const int warp = tid >> 5;
    const int lane = tid & 31;
    const int wm   = warp & 3;    // 4 m-groups of 32 q-rows
    const int wn   = warp >> 2;   // 2 n-groups (keys / dh halves)
    const int qb = blockIdx.x, h = blockIdx.y, b = blockIdx.z;
    const int bh = b * HEADS + h;

    const __nv_bfloat16* Qh = g_qhi + (size_t)bh * NSEQ * DH;
    const __nv_bfloat16* Ql = g_qlo + (size_t)bh * NSEQ * DH;
    const __nv_bfloat16* Vh = g_vhi + (size_t)bh * DH * NSEQ;
    const __nv_bfloat16* Vl = g_vlo + (size_t)bh * DH * NSEQ;
    const float* sqg = g_sq + (size_t)bh * NSEQ;

    const int fr = (lane & 7) + ((lane >> 3) & 1) * 8;
    const int fc = (lane >> 4) * 8;
    const int r4 = lane >> 2;
    const int c2 = (lane & 3) * 2;

    const float C = 0.18033688011112042f;  // log2(e)/8

    // sqn*C for this thread's 4 output rows
    float sqnC[2][2];
#pragma unroll
    for (int mt = 0; mt < 2; mt++) {
        sqnC[mt][0] = sqg[qb * 128 + wm * 32 + mt * 16 + r4]     * C;
        sqnC[mt][1] = sqg[qb * 128 + wm * 32 + mt * 16 + r4 + 8] * C;
    }

    // issue Q tile (rows qb*128.., stride 144B in smem)
    for (int s = tid; s < 128 * 8; s += 256) {
        int row = s >> 3, seg = s & 7;
        CP_ASYNC16(sb + A_SQH + row * 144 + seg * 16,
                   Qh + (size_t)(qb * 128 + row) * DH + seg * 8);
        CP_ASYNC16(sb + A_SQL + row * 144 + seg * 16,
                   Ql + (size_t)(qb * 128 + row) * DH + seg * 8);
    }

    auto issue_tile = [&](int t) {
        const uint32_t stb = sb + A_ST0 + (t & 1) * A_STSZ;
        for (int s = tid; s < 64 * 8; s += 256) {
            int row = s >> 3, seg = s & 7;
            CP_ASYNC16(stb + A_KH + row * 144 + seg * 16,
                       Qh + (size_t)(t * 64 + row) * DH + seg * 8);
            CP_ASYNC16(stb + A_KL + row * 144 + seg * 16,
                       Ql + (size_t)(t * 64 + row) * DH + seg * 8);
            CP_ASYNC16(stb + A_VH + row * 144 + seg * 16,
                       Vh + (size_t)row * NSEQ + t * 64 + seg * 8);
            CP_ASYNC16(stb + A_VL + row * 144 + seg * 16,
                       Vl + (size_t)row * NSEQ + t * 64 + seg * 8);
        }
        if (tid < 16)
            CP_ASYNC16(stb + A_SQS + tid * 16, sqg + t * 64 + tid * 4);
        CP_COMMIT();
    };

    issue_tile(0);  // commits Q too

    float acc[2][4][4];
#pragma unroll
    for (int i = 0; i < 2; i++)
#pragma unroll
        for (int j = 0; j < 4; j++)
#pragma unroll
            for (int c = 0; c < 4; c++) acc[i][j][c] = 0.0f;
    float lacc[2][2] = {{0.f, 0.f}, {0.f, 0.f}};

    for (int t = 0; t < NSEQ / 64; t++) {
        if (t + 1 < NSEQ / 64) { issue_tile(t + 1); CP_WAIT(1); }
        else                   { CP_WAIT(0); }
        __syncthreads();

        const uint32_t kb = sb + A_ST0 + (t & 1) * A_STSZ;
        const float* sqs = (const float*)(sm + A_ST0 + (t & 1) * A_STSZ + A_SQS);

        // ---- QK + softmax, one mt (16 q-rows) at a time --------------------
#pragma unroll
        for (int mt = 0; mt < 2; mt++) {
            float S[4][4];
#pragma unroll
            for (int j = 0; j < 4; j++)
#pragma unroll
                for (int c = 0; c < 4; c++) S[j][c] = 0.0f;

#pragma unroll
            for (int kc = 0; kc < 4; kc++) {
                const int colb = (kc * 16 + fc) * 2;
                uint32_t kh[2][4], kl[2][4];
#pragma unroll
                for (int np = 0; np < 2; np++) {
                    const int row = wn * 32 + np * 16 + fr;
                    LDSM_X4(kh[np][0], kh[np][1], kh[np][2], kh[np][3],
                            kb + A_KH + row * 144 + colb);
                    LDSM_X4(kl[np][0], kl[np][1], kl[np][2], kl[np][3],
                            kb + A_KL + row * 144 + colb);
                }
                const int arow = wm * 32 + mt * 16 + fr;
                uint32_t ah[4], al[4];
                LDSM_X4(ah[0], ah[1], ah[2], ah[3], sb + A_SQH + arow * 144 + colb);
                LDSM_X4(al[0], al[1], al[2], al[3], sb + A_SQL + arow * 144 + colb);
#pragma unroll
                for (int nt = 0; nt < 4; nt++) {
                    const int np = nt >> 1, sub = nt & 1;
                    MMA16816(S[nt], ah, kh[np][sub], kh[np][sub + 2]);
                    MMA16816(S[nt], ah, kl[np][sub], kl[np][sub + 2]);
                    MMA16816(S[nt], al, kh[np][sub], kh[np][sub + 2]);
                }
            }

            // softmax + pack + STS
#pragma unroll
            for (int nt = 0; nt < 4; nt++) {
                const int col = wn * 32 + nt * 8 + c2;
                const float sqm0 = sqs[col], sqm1 = sqs[col + 1];
                float p0 = ex2(fmaf(fmaf(2.f, S[nt][0], -sqm0), C, -sqnC[mt][0]));
                float p1 = ex2(fmaf(fmaf(2.f, S[nt][1], -sqm1), C, -sqnC[mt][0]));
                float p2 = ex2(fmaf(fmaf(2.f, S[nt][2], -sqm0), C, -sqnC[mt][1]));
                float p3 = ex2(fmaf(fmaf(2.f, S[nt][3], -sqm1), C, -sqnC[mt][1]));
                lacc[mt][0] += p0 + p1;
                lacc[mt][1] += p2 + p3;
                const int row = wm * 32 + mt * 16 + r4;
                const uint32_t cb = col * 2;
                STS32(sb + A_PH + row * 144 + cb,       pack_hi2(p0, p1));
                STS32(sb + A_PH + (row + 8) * 144 + cb, pack_hi2(p2, p3));
                STS32(sb + A_PL + row * 144 + cb,       pack_lo2(p0, p1));
                STS32(sb + A_PL + (row + 8) * 144 + cb, pack_lo2(p2, p3));
            }
        }
        __syncthreads();

        // ---- PV: out[128 x 64dh] += P[128 x 64] * Vt[64dh x 64]^T ---------
#pragma unroll
        for (int kc = 0; kc < 4; kc++) {
            const int colb = (kc * 16 + fc) * 2;
            uint32_t vh[2][4], vl[2][4];
#pragma unroll
            for (int np = 0; np < 2; np++) {
                const int row = wn * 32 + np * 16 + fr;
                LDSM_X4(vh[np][0], vh[np][1], vh[np][2], vh[np][3],
                        kb + A_VH + row * 144 + colb);
                LDSM_X4(vl[np][0], vl[np][1], vl[np][2], vl[np][3],
                        kb + A_VL + row * 144 + colb);
            }
#pragma unroll
            for (int mt = 0; mt < 2; mt++) {
                const int arow = wm * 32 + mt * 16 + fr;
                uint32_t ph[4], pl[4];
                LDSM_X4(ph[0], ph[1], ph[2], ph[3], sb + A_PH + arow * 144 + colb);
                LDSM_X4(pl[0], pl[1], pl[2], pl[3], sb + A_PL + arow * 144 + colb);
#pragma unroll
                for (int nt = 0; nt < 4; nt++) {
                    const int np = nt >> 1, sub = nt & 1;
                    MMA16816(acc[mt][nt], ph, vh[np][sub], vh[np][sub + 2]);
                    MMA16816(acc[mt][nt], ph, vl[np][sub], vl[np][sub + 2]);
                    MMA16816(acc[mt][nt], pl, vh[np][sub], vh[np][sub + 2]);
                }
            }
        }
        __syncthreads();  // P/K/V stage reuse protection
    }

    // ---- l reduction across quads and the two wn warps ---------------------
    float* l2d = (float*)(sm + A_L2D);
#pragma unroll
    for (int mt = 0; mt < 2; mt++)
#pragma unroll
        for (int hf = 0; hf < 2; hf++) {
            float l = lacc[mt][hf];
            l += __shfl_xor_sync(0xffffffffu, l, 1);
            l += __shfl_xor_sync(0xffffffffu, l, 2);
            if ((lane & 3) == 0)
                l2d[wn * 128 + wm * 32 + mt * 16 + hf * 8 + r4] = l;
        }
    __syncthreads();

    // ---- epilogue: normalize, split to bf16 hi/lo, write to gemm-A ---------
#pragma unroll
    for (int mt = 0; mt < 2; mt++) {
#pragma unroll
        for (int hf = 0; hf < 2; hf++) {
            const int row = wm * 32 + mt * 16 + hf * 8 + r4;
            const float linv = 1.0f / (l2d[row] + l2d[128 + row]);
            const int n = qb * 128 + row;
#pragma unroll
            for (int nt = 0; nt < 4; nt++) {
                const int dcol = h * DH + wn * 32 + nt * 8 + c2;
                const float vx = acc[mt][nt][hf * 2 + 0] * linv;
                const float vy = acc[mt][nt][hf * 2 + 1] * linv;
                size_t idx = ((size_t)b * NSEQ + n) * DIMV + dcol;
                *(uint32_t*)(g_ahi + idx) = pack_hi2(vx, vy);
                *(uint32_t*)(g_alo + idx) = pack_lo2(vx, vy);
            }
        }
    }
}

// ---------------------------------------------------------------------------

extern "C" void kernel_launch(void* const* d_in, const int* in_sizes, int n_in,
                              void* d_out, int out_size)
{
    const float* x    = (const float*)d_in[0];   // [2,2048,1024]
    const float* w_qv = (const float*)d_in[1];   // [2048,1024]
    const float* w_o  = (const float*)d_in[2];   // [1024,1024]
    float* out = (float*)d_out;                  // [2,2048,1024]

    cudaFuncSetAttribute(mma_gemm, cudaFuncAttributeMaxDynamicSharedMemorySize,
                         GEMM_SMEM);
    cudaFuncSetAttribute(mma_attn, cudaFuncAttributeMaxDynamicSharedMemorySize,
                         ATT_SMEM);

    // 1) split x -> A pair, w_qv -> B pair
    split_kernel<<<4096 * 1024 / 8 / 256, 256>>>(x, 0, 4096 * 1024);
    split_kernel<<<2048 * 1024 / 8 / 256, 256>>>(w_qv, 1, 2048 * 1024);

    // 2) QV projection -> q/v bf16 splits (v transposed)
    mma_gemm<<<dim3(16, 32), 256, GEMM_SMEM>>>(nullptr, 0, 1);

    // 3) split w_o -> B pair; ||q||^2
    split_kernel<<<1024 * 1024 / 8 / 256, 256>>>(w_o, 1, 1024 * 1024);
    sq_kernel<<<(BATCH * HEADS * NSEQ) / 256, 256>>>();

    // 4) tensor-core attention -> writes split output into A pair
    mma_attn<<<dim3(NSEQ / 128, HEADS, BATCH), 256, ATT_SMEM>>>();

    // 5) Wo projection -> out
    mma_gemm<<<dim3(8, 32), 256, GEMM_SMEM>>>(out, 1024, 0);
}

// round 12
// speedup vs baseline: 3.1714x; 1.2814x over previous
// R11: attention MMA diet: QK drops Q-lo (S = Qh·K), PV drops P-lo with
//      l summed from rounded Ph (normalization cancels weight errors).
//      192->128 MMAs/warp/tile; smem 149.5->109.5KB -> 2 CTAs/SM.
#include <cuda_runtime.h>
#include <cuda_bf16.h>
#include <cstdint>

#define BATCH 2
#define NSEQ  2048
#define DIMV  1024
#define HEADS 16
#define DH    64

// ---------------- scratch (device globals; total 56.25 MB) ------------------
__device__ float g_sq[BATCH * HEADS * NSEQ];                    // 0.25 MB
__device__ __nv_bfloat16 g_qhi[BATCH * HEADS * NSEQ * DH];      // 8 MB  [bh][n][d]
__device__ __nv_bfloat16 g_qlo[BATCH * HEADS * NSEQ * DH];      // 8 MB
__device__ __nv_bfloat16 g_vhi[BATCH * HEADS * DH * NSEQ];      // 8 MB  [bh][d][n]
__device__ __nv_bfloat16 g_vlo[BATCH * HEADS * DH * NSEQ];      // 8 MB
__device__ __nv_bfloat16 g_ahi[4096 * 1024];                    // 8 MB  gemm A
__device__ __nv_bfloat16 g_alo[4096 * 1024];                    // 8 MB
__device__ __nv_bfloat16 g_bhi[2048 * 1024];                    // 4 MB  gemm B
__device__ __nv_bfloat16 g_blo[2048 * 1024];                    // 4 MB

// ---------------- helpers ---------------------------------------------------
__device__ __forceinline__ uint32_t smem_u32(const void* p) {
    uint32_t a;
    asm("{ .reg .u64 t; cvta.to.shared.u64 t, %1; cvt.u32.u64 %0, t; }"
        : "=r"(a) : "l"(p));
    return a;
}
#define LDSM_X4(r0, r1, r2, r3, addr)                                        \
    asm volatile("ldmatrix.sync.aligned.m8n8.x4.shared.b16 {%0,%1,%2,%3}, [%4];" \
                 : "=r"(r0), "=r"(r1), "=r"(r2), "=r"(r3) : "r"(addr))
#define MMA16816(d, a, b0, b1)                                               \
    asm volatile("mma.sync.aligned.m16n8k16.row.col.f32.bf16.bf16.f32 "      \
                 "{%0,%1,%2,%3}, {%4,%5,%6,%7}, {%8,%9}, {%0,%1,%2,%3};"     \
                 : "+f"((d)[0]), "+f"((d)[1]), "+f"((d)[2]), "+f"((d)[3])    \
                 : "r"((a)[0]), "r"((a)[1]), "r"((a)[2]), "r"((a)[3]),       \
                   "r"(b0), "r"(b1))
#define CP_ASYNC16(dst, src)                                                 \
    asm volatile("cp.async.cg.shared.global [%0], [%1], 16;"                 \
                 :: "r"(dst), "l"(src))
#define CP_COMMIT() asm volatile("cp.async.commit_group;" ::: "memory")
#define CP_WAIT(n)  asm volatile("cp.async.wait_group %0;" :: "n"(n) : "memory")
#define STS32(addr, v)                                                       \
    asm volatile("st.shared.u32 [%0], %1;" :: "r"(addr), "r"(v) : "memory")

union BU { __nv_bfloat162 b; uint32_t u; };
__device__ __forceinline__ uint32_t pack_hi2(float x, float y) {
    BU t; t.b = __floats2bfloat162_rn(x, y); return t.u;
}
__device__ __forceinline__ uint32_t pack_lo2(float x, float y) {
    float rx = x - __bfloat162float(__float2bfloat16(x));
    float ry = y - __bfloat162float(__float2bfloat16(y));
    BU t; t.b = __floats2bfloat162_rn(rx, ry); return t.u;
}
__device__ __forceinline__ float ex2(float x) {
    float y; asm("ex2.approx.ftz.f32 %0, %1;" : "=f"(y) : "f"(x)); return y;
}

// ---------------------------------------------------------------------------
// split fp32 -> bf16 hi + lo. which=0 -> (g_ahi,g_alo); which=1 -> (g_bhi,g_blo)
// ---------------------------------------------------------------------------
__global__ __launch_bounds__(256) void split_kernel(const float* __restrict__ src,
                                                    int which, int n)
{
    int i = (blockIdx.x * 256 + threadIdx.x) * 8;
    if (i >= n) return;
    __nv_bfloat16* hi = which ? g_bhi : g_ahi;
    __nv_bfloat16* lo = which ? g_blo : g_alo;
    float4 a = *(const float4*)(src + i);
    float4 b = *(const float4*)(src + i + 4);
    uint4 hv, lv;
    hv.x = pack_hi2(a.x, a.y);  hv.y = pack_hi2(a.z, a.w);
    hv.z = pack_hi2(b.x, b.y);  hv.w = pack_hi2(b.z, b.w);
    lv.x = pack_lo2(a.x, a.y);  lv.y = pack_lo2(a.z, a.w);
    lv.z = pack_lo2(b.x, b.y);  lv.w = pack_lo2(b.z, b.w);
    *(uint4*)(hi + i) = hv;
    *(uint4*)(lo + i) = lv;
}

// ---------------------------------------------------------------------------
// mma.sync bf16x3 GEMM (NT). mode 0: C[m*ldc+n]. mode 1: scatter q/v splits.
// ---------------------------------------------------------------------------
#define KDIM   1024
#define SROW   40
#define ABYTES (128 * SROW * 2)
#define STAGEB (4 * ABYTES)
#define GEMM_SMEM (2 * STAGEB)

__global__ __launch_bounds__(256, 1) void mma_gemm(float* __restrict__ C,
                                                   int ldc, int mode)
{
    extern __shared__ char smem[];
    const uint32_t sbase = smem_u32(smem);

    const int tid  = threadIdx.x;
    const int warp = tid >> 5;
    const int lane = tid & 31;
    const int wm   = warp & 1;
    const int wn   = warp >> 1;

    const int m0 = blockIdx.y * 128;
    const int n0 = blockIdx.x * 128;

    const int lrow  = tid >> 1;
    const int lhalf = (tid & 1) * 16;
    const __nv_bfloat16* pAh = g_ahi + (size_t)(m0 + lrow) * KDIM + lhalf;
    const __nv_bfloat16* pAl = g_alo + (size_t)(m0 + lrow) * KDIM + lhalf;
    const __nv_bfloat16* pBh = g_bhi + (size_t)(n0 + lrow) * KDIM + lhalf;
    const __nv_bfloat16* pBl = g_blo + (size_t)(n0 + lrow) * KDIM + lhalf;
    const uint32_t so = (uint32_t)(lrow * SROW + lhalf) * 2;

    const int fr = (lane & 7) + ((lane >> 3) & 1) * 8;
    const int fc = (lane >> 4) * 8;

    float acc[4][4][4];
#pragma unroll
    for (int i = 0; i < 4; i++)
#pragma unroll
        for (int j = 0; j < 4; j++)
#pragma unroll
            for (int c = 0; c < 4; c++) acc[i][j][c] = 0.0f;

#define ISSUE(ch) do {                                                       \
        const uint32_t st = sbase + ((ch) & 1) * STAGEB + so;                \
        const int ko = (ch) * 32;                                            \
        CP_ASYNC16(st,                  pAh + ko);                           \
        CP_ASYNC16(st + 16,             pAh + ko + 8);                       \
        CP_ASYNC16(st + ABYTES,         pAl + ko);                           \
        CP_ASYNC16(st + ABYTES + 16,    pAl + ko + 8);                       \
        CP_ASYNC16(st + 2 * ABYTES,      pBh + ko);                          \
        CP_ASYNC16(st + 2 * ABYTES + 16, pBh + ko + 8);                      \
        CP_ASYNC16(st + 3 * ABYTES,      pBl + ko);                          \
        CP_ASYNC16(st + 3 * ABYTES + 16, pBl + ko + 8);                      \
        CP_COMMIT();                                                         \
    } while (0)

    ISSUE(0);

    for (int ch = 0; ch < KDIM / 32; ch++) {
        if (ch + 1 < KDIM / 32) { ISSUE(ch + 1); CP_WAIT(1); }
        else                    { CP_WAIT(0); }
        __syncthreads();

        const char* stg = smem + (ch & 1) * STAGEB;
        const __nv_bfloat16* sAh = (const __nv_bfloat16*)(stg);
        const __nv_bfloat16* sAl = (const __nv_bfloat16*)(stg + ABYTES);
        const __nv_bfloat16* sBh = (const __nv_bfloat16*)(stg + 2 * ABYTES);
        const __nv_bfloat16* sBl = (const __nv_bfloat16*)(stg + 3 * ABYTES);

#pragma unroll
        for (int ks = 0; ks < 2; ks++) {
            const int kc = ks * 16 + fc;
            uint32_t bh[2][4], bl[2][4];
#pragma unroll
            for (int np = 0; np < 2; np++) {
                const int row = wn * 32 + np * 16 + fr;
                LDSM_X4(bh[np][0], bh[np][1], bh[np][2], bh[np][3],
                        smem_u32(sBh + row * SROW + kc));
                LDSM_X4(bl[np][0], bl[np][1], bl[np][2], bl[np][3],
                        smem_u32(sBl + row * SROW + kc));
            }
#pragma unroll
            for (int mt = 0; mt < 4; mt++) {
                const int row = wm * 64 + mt * 16 + fr;
                uint32_t ah[4], al[4];
                LDSM_X4(ah[0], ah[1], ah[2], ah[3],
                        smem_u32(sAh + row * SROW + kc));
                LDSM_X4(al[0], al[1], al[2], al[3],
                        smem_u32(sAl + row * SROW + kc));
#pragma unroll
                for (int nt = 0; nt < 4; nt++) {
                    const int np = nt >> 1, sub = nt & 1;
                    const uint32_t b0h = bh[np][sub], b1h = bh[np][sub + 2];
                    const uint32_t b0l = bl[np][sub], b1l = bl[np][sub + 2];
                    MMA16816(acc[mt][nt], ah, b0h, b1h);
                    MMA16816(acc[mt][nt], ah, b0l, b1l);
                    MMA16816(acc[mt][nt], al, b0h, b1h);
                }
            }
        }
        __syncthreads();
    }

    const int r0 = lane >> 2;
    const int c0 = (lane & 3) * 2;
#pragma unroll
    for (int mt = 0; mt < 4; mt++) {
#pragma unroll
        for (int half = 0; half < 2; half++) {
            const int m = m0 + wm * 64 + mt * 16 + r0 + half * 8;
#pragma unroll
            for (int nt = 0; nt < 4; nt++) {
                const int e = n0 + wn * 32 + nt * 8 + c0;
                float vx = acc[mt][nt][half * 2 + 0];
                float vy = acc[mt][nt][half * 2 + 1];
                if (mode == 0) {
                    float2 v; v.x = vx; v.y = vy;
                    *(float2*)(C + (size_t)m * ldc + e) = v;
                } else {
                    const int bb = m >> 11, nn = m & 2047;
                    if (e < DIMV) {
                        const int hh = e >> 6, d0 = e & 63;
                        size_t idx = (((size_t)(bb * HEADS + hh)) * NSEQ + nn) * DH + d0;
                        *(uint32_t*)(g_qhi + idx) = pack_hi2(vx, vy);
                        *(uint32_t*)(g_qlo + idx) = pack_lo2(vx, vy);
                    } else {
                        const int e2 = e - DIMV;
                        const int hh = e2 >> 6, d0 = e2 & 63;
                        size_t bs = ((size_t)(bb * HEADS + hh)) * DH;
                        __nv_bfloat16 hx = __float2bfloat16(vx);
                        __nv_bfloat16 hy = __float2bfloat16(vy);
                        g_vhi[(bs + d0)     * NSEQ + nn] = hx;
                        g_vhi[(bs + d0 + 1) * NSEQ + nn] = hy;
                        g_vlo[(bs + d0)     * NSEQ + nn] =
                            __float2bfloat16(vx - __bfloat162float(hx));
                        g_vlo[(bs + d0 + 1) * NSEQ + nn] =
                            __float2bfloat16(vy - __bfloat162float(hy));
                    }
                }
            }
        }
    }
}

// ---------------------------------------------------------------------------
// ||q||^2 per row from the split representation (consistent with QK mma)
// ---------------------------------------------------------------------------
__global__ __launch_bounds__(256) void sq_kernel()
{
    int row = blockIdx.x * blockDim.x + threadIdx.x;
    if (row >= BATCH * HEADS * NSEQ) return;
    const uint32_t* ph = (const uint32_t*)(g_qhi + (size_t)row * DH);
    const uint32_t* pl = (const uint32_t*)(g_qlo + (size_t)row * DH);
    float s = 0.0f;
#pragma unroll
    for (int i = 0; i < 32; i++) {
        BU uh; uh.u = ph[i];
        BU ul; ul.u = pl[i];
        float2 fh = __bfloat1622float2(uh.b);
        float2 fl = __bfloat1622float2(ul.b);
        float x = fh.x + fl.x, y = fh.y + fl.y;
        s += x * x + y * y;
    }
    g_sq[row] = s;
}

// ---------------------------------------------------------------------------
// mma.sync L2 attention, reduced precision where softmax spikiness allows:
//   S = Qh·(Kh+Kl)  (Q-lo dropped: exponent err ~0.008, cancels in softmax)
//   P stored as bf16 Ph only; l summed from ROUNDED Ph (consistent weights)
//   PV = Ph·Vh + Ph·Vl  (V-lo kept: feeds output directly)
// 128 MMAs/warp/tile. smem 109.5KB -> 2 CTAs/SM.
// ---------------------------------------------------------------------------
#define A_SQH  0                     // Q hi: 128*144 = 18432
#define A_ST0  18432                 // stages: 2 x 37120
#define A_STSZ 37120
#define A_KH   0
#define A_KL   9216
#define A_VH   18432
#define A_VL   27648
#define A_SQS  36864
#define A_PH   92672                 // 128*144 = 18432
#define A_L2D  111104                // 256 floats
#define ATT_SMEM 112128

__global__ __launch_bounds__(256, 2) void mma_attn()
{
    extern __shared__ char sm[];
    const uint32_t sb = smem_u32(sm);
    const int tid  = threadIdx.x;
    const int warp = tid >> 5;
    const int lane = tid & 31;
    const int wm   = warp & 3;    // 4 m-groups of 32 q-rows
    const int wn   = warp >> 2;   // 2 n-groups (keys / dh halves)
    const int qb = blockIdx.x, h = blockIdx.y, b = blockIdx.z;
    const int bh = b * HEADS + h;

    const __nv_bfloat16* Qh = g_qhi + (size_t)bh * NSEQ * DH;
    const __nv_bfloat16* Ql = g_qlo + (size_t)bh * NSEQ * DH;
    const __nv_bfloat16* Vh = g_vhi + (size_t)bh * DH * NSEQ;
    const __nv_bfloat16* Vl = g_vlo + (size_t)bh * DH * NSEQ;
    const float* sqg = g_sq + (size_t)bh * NSEQ;

    const int fr = (lane & 7) + ((lane >> 3) & 1) * 8;
    const int fc = (lane >> 4) * 8;
    const int r4 = lane >> 2;
    const int c2 = (lane & 3) * 2;

    const float C = 0.18033688011112042f;  // log2(e)/8

    float sqnC[2][2];
#pragma unroll
    for (int mt = 0; mt < 2; mt++) {
        sqnC[mt][0] = sqg[qb * 128 + wm * 32 + mt * 16 + r4]     * C;
        sqnC[mt][1] = sqg[qb * 128 + wm * 32 + mt * 16 + r4 + 8] * C;
    }

    // issue Q hi tile (rows qb*128..; 144B smem stride)
    for (int s = tid; s < 128 * 8; s += 256) {
        int row = s >> 3, seg = s & 7;
        CP_ASYNC16(sb + A_SQH + row * 144 + seg * 16,
                   Qh + (size_t)(qb * 128 + row) * DH + seg * 8);
    }

    auto issue_tile = [&](int t) {
        const uint32_t stb = sb + A_ST0 + (t & 1) * A_STSZ;
        for (int s = tid; s < 64 * 8; s += 256) {
            int row = s >> 3, seg = s & 7;
            CP_ASYNC16(stb + A_KH + row * 144 + seg * 16,
                       Qh + (size_t)(t * 64 + row) * DH + seg * 8);
            CP_ASYNC16(stb + A_KL + row * 144 + seg * 16,
                       Ql + (size_t)(t * 64 + row) * DH + seg * 8);
            CP_ASYNC16(stb + A_VH + row * 144 + seg * 16,
                       Vh + (size_t)row * NSEQ + t * 64 + seg * 8);
            CP_ASYNC16(stb + A_VL + row * 144 + seg * 16,
                       Vl + (size_t)row * NSEQ + t * 64 + seg * 8);
        }
        if (tid < 16)
            CP_ASYNC16(stb + A_SQS + tid * 16, sqg + t * 64 + tid * 4);
        CP_COMMIT();
    };

    issue_tile(0);  // commits Q too

    float acc[2][4][4];
#pragma unroll
    for (int i = 0; i < 2; i++)
#pragma unroll
        for (int j = 0; j < 4; j++)
#pragma unroll
            for (int c = 0; c < 4; c++) acc[i][j][c] = 0.0f;
    float lacc[2][2] = {{0.f, 0.f}, {0.f, 0.f}};

    for (int t = 0; t < NSEQ / 64; t++) {
        if (t + 1 < NSEQ / 64) { issue_tile(t + 1); CP_WAIT(1); }
        else                   { CP_WAIT(0); }
        __syncthreads();

        const uint32_t kb = sb + A_ST0 + (t & 1) * A_STSZ;
        const float* sqs = (const float*)(sm + A_ST0 + (t & 1) * A_STSZ + A_SQS);

        // ---- QK: S[mt] = Qh x (Kh + Kl), kc outer with K frags hoisted ----
        float S[2][4][4];
#pragma unroll
        for (int i = 0; i < 2; i++)
#pragma unroll
            for (int j = 0; j < 4; j++)
#pragma unroll
                for (int c = 0; c < 4; c++) S[i][j][c] = 0.0f;

#pragma unroll
        for (int kc = 0; kc < 4; kc++) {
            const int colb = (kc * 16 + fc) * 2;
            uint32_t kh[2][4], kl[2][4];
#pragma unroll
            for (int np = 0; np < 2; np++) {
                const int row = wn * 32 + np * 16 + fr;
                LDSM_X4(kh[np][0], kh[np][1], kh[np][2], kh[np][3],
                        kb + A_KH + row * 144 + colb);
                LDSM_X4(kl[np][0], kl[np][1], kl[np][2], kl[np][3],
                        kb + A_KL + row * 144 + colb);
            }
#pragma unroll
            for (int mt = 0; mt < 2; mt++) {
                const int arow = wm * 32 + mt * 16 + fr;
                uint32_t ah[4];
                LDSM_X4(ah[0], ah[1], ah[2], ah[3], sb + A_SQH + arow * 144 + colb);
#pragma unroll
                for (int nt = 0; nt < 4; nt++) {
                    const int np = nt >> 1, sub = nt & 1;
                    MMA16816(S[mt][nt], ah, kh[np][sub], kh[np][sub + 2]);
                    MMA16816(S[mt][nt], ah, kl[np][sub], kl[np][sub + 2]);
                }
            }
        }

        // ---- softmax (analytic max 0), pack Ph, l from ROUNDED Ph ---------
#pragma unroll
        for (int mt = 0; mt < 2; mt++) {
#pragma unroll
            for (int nt = 0; nt < 4; nt++) {
                const int col = wn * 32 + nt * 8 + c2;
                const float sqm0 = sqs[col], sqm1 = sqs[col + 1];
                float p0 = ex2(fmaf(fmaf(2.f, S[mt][nt][0], -sqm0), C, -sqnC[mt][0]));
                float p1 = ex2(fmaf(fmaf(2.f, S[mt][nt][1], -sqm1), C, -sqnC[mt][0]));
                float p2 = ex2(fmaf(fmaf(2.f, S[mt][nt][2], -sqm0), C, -sqnC[mt][1]));
                float p3 = ex2(fmaf(fmaf(2.f, S[mt][nt][3], -sqm1), C, -sqnC[mt][1]));
                const uint32_t u01 = pack_hi2(p0, p1);
                const uint32_t u23 = pack_hi2(p2, p3);
                lacc[mt][0] += __uint_as_float(u01 << 16) +
                               __uint_as_float(u01 & 0xffff0000u);
                lacc[mt][1] += __uint_as_float(u23 << 16) +
                               __uint_as_float(u23 & 0xffff0000u);
                const int row = wm * 32 + mt * 16 + r4;
                const uint32_t cb = col * 2;
                STS32(sb + A_PH + row * 144 + cb,       u01);
                STS32(sb + A_PH + (row + 8) * 144 + cb, u23);
            }
        }
        __syncthreads();

        // ---- PV: out += Ph x (Vh + Vl) ------------------------------------
#pragma unroll
        for (int kc = 0; kc < 4; kc++) {
            const int colb = (kc * 16 + fc) * 2;
            uint32_t vh[2][4], vl[2][4];
#pragma unroll
            for (int np = 0; np < 2; np++) {
                const int row = wn * 32 + np * 16 + fr;
                LDSM_X4(vh[np][0], vh[np][1], vh[np][2], vh[np][3],
                        kb + A_VH + row * 144 + colb);
                LDSM_X4(vl[np][0], vl[np][1], vl[np][2], vl[np][3],
                        kb + A_VL + row * 144 + colb);
            }
#pragma unroll
            for (int mt = 0; mt < 2; mt++) {
                const int arow = wm * 32 + mt * 16 + fr;
                uint32_t ph[4];
                LDSM_X4(ph[0], ph[1], ph[2], ph[3], sb + A_PH + arow * 144 + colb);
#pragma unroll
                for (int nt = 0; nt < 4; nt++) {
                    const int np = nt >> 1, sub = nt & 1;
                    MMA16816(acc[mt][nt], ph, vh[np][sub], vh[np][sub + 2]);
                    MMA16816(acc[mt][nt], ph, vl[np][sub], vl[np][sub + 2]);
                }
            }
        }
        __syncthreads();  // stage/P reuse protection
    }

    // ---- l reduction across quads and the two wn warps ---------------------
    float* l2d = (float*)(sm + A_L2D);
#pragma unroll
    for (int mt = 0; mt < 2; mt++)
#pragma unroll
        for (int hf = 0; hf < 2; hf++) {
            float l = lacc[mt][hf];
            l += __shfl_xor_sync(0xffffffffu, l, 1);
            l += __shfl_xor_sync(0xffffffffu, l, 2);
            if ((lane & 3) == 0)
                l2d[wn * 128 + wm * 32 + mt * 16 + hf * 8 + r4] = l;
        }
    __syncthreads();

    // ---- epilogue: normalize, split to bf16 hi/lo, write to gemm-A ---------
#pragma unroll
    for (int mt = 0; mt < 2; mt++) {
#pragma unroll
        for (int hf = 0; hf < 2; hf++) {
            const int row = wm * 32 + mt * 16 + hf * 8 + r4;
            const float linv = 1.0f / (l2d[row] + l2d[128 + row]);
            const int n = qb * 128 + row;
#pragma unroll
            for (int nt = 0; nt < 4; nt++) {
                const int dcol = h * DH + wn * 32 + nt * 8 + c2;
                const float vx = acc[mt][nt][hf * 2 + 0] * linv;
                const float vy = acc[mt][nt][hf * 2 + 1] * linv;
                size_t idx = ((size_t)b * NSEQ + n) * DIMV + dcol;
                *(uint32_t*)(g_ahi + idx) = pack_hi2(vx, vy);
                *(uint32_t*)(g_alo + idx) = pack_lo2(vx, vy);
            }
        }
    }
}

// ---------------------------------------------------------------------------

extern "C" void kernel_launch(void* const* d_in, const int* in_sizes, int n_in,
                              void* d_out, int out_size)
{
    const float* x    = (const float*)d_in[0];   // [2,2048,1024]
    const float* w_qv = (const float*)d_in[1];   // [2048,1024]
    const float* w_o  = (const float*)d_in[2];   // [1024,1024]
    float* out = (float*)d_out;                  // [2,2048,1024]

    cudaFuncSetAttribute(mma_gemm, cudaFuncAttributeMaxDynamicSharedMemorySize,
                         GEMM_SMEM);
    cudaFuncSetAttribute(mma_attn, cudaFuncAttributeMaxDynamicSharedMemorySize,
                         ATT_SMEM);

    // 1) split x -> A pair, w_qv -> B pair
    split_kernel<<<4096 * 1024 / 8 / 256, 256>>>(x, 0, 4096 * 1024);
    split_kernel<<<2048 * 1024 / 8 / 256, 256>>>(w_qv, 1, 2048 * 1024);

    // 2) QV projection -> q/v bf16 splits (v transposed)
    mma_gemm<<<dim3(16, 32), 256, GEMM_SMEM>>>(nullptr, 0, 1);

    // 3) split w_o -> B pair; ||q||^2
    split_kernel<<<1024 * 1024 / 8 / 256, 256>>>(w_o, 1, 1024 * 1024);
    sq_kernel<<<(BATCH * HEADS * NSEQ) / 256, 256>>>();

    // 4) tensor-core attention -> writes split output into A pair
    mma_attn<<<dim3(NSEQ / 128, HEADS, BATCH), 256, ATT_SMEM>>>();

    // 5) Wo projection -> out
    mma_gemm<<<dim3(8, 32), 256, GEMM_SMEM>>>(out, 1024, 0);
}

// round 13
// speedup vs baseline: 3.8906x; 1.2268x over previous
// R12: fp16 single-precision attention (Q,K,V,P all fp16; 64 MMAs/warp/tile,
//      half of R11). sq from fp16-rounded q keeps analytic max = 0. GEMMs
//      stay bf16x3. Globals 40.25MB.
#include <cuda_runtime.h>
#include <cuda_bf16.h>
#include <cuda_fp16.h>
#include <cstdint>

#define BATCH 2
#define NSEQ  2048
#define DIMV  1024
#define HEADS 16
#define DH    64

// ---------------- scratch (device globals; total 40.25 MB) ------------------
__device__ float g_sq[BATCH * HEADS * NSEQ];                    // 0.25 MB
__device__ __half g_q16[BATCH * HEADS * NSEQ * DH];             // 8 MB [bh][n][d]
__device__ __half g_v16[BATCH * HEADS * DH * NSEQ];             // 8 MB [bh][d][n]
__device__ __nv_bfloat16 g_ahi[4096 * 1024];                    // 8 MB  gemm A
__device__ __nv_bfloat16 g_alo[4096 * 1024];                    // 8 MB
__device__ __nv_bfloat16 g_bhi[2048 * 1024];                    // 4 MB  gemm B
__device__ __nv_bfloat16 g_blo[2048 * 1024];                    // 4 MB

// ---------------- helpers ---------------------------------------------------
__device__ __forceinline__ uint32_t smem_u32(const void* p) {
    uint32_t a;
    asm("{ .reg .u64 t; cvta.to.shared.u64 t, %1; cvt.u32.u64 %0, t; }"
        : "=r"(a) : "l"(p));
    return a;
}
#define LDSM_X4(r0, r1, r2, r3, addr)                                        \
    asm volatile("ldmatrix.sync.aligned.m8n8.x4.shared.b16 {%0,%1,%2,%3}, [%4];" \
                 : "=r"(r0), "=r"(r1), "=r"(r2), "=r"(r3) : "r"(addr))
#define MMA16816(d, a, b0, b1)                                               \
    asm volatile("mma.sync.aligned.m16n8k16.row.col.f32.bf16.bf16.f32 "      \
                 "{%0,%1,%2,%3}, {%4,%5,%6,%7}, {%8,%9}, {%0,%1,%2,%3};"     \
                 : "+f"((d)[0]), "+f"((d)[1]), "+f"((d)[2]), "+f"((d)[3])    \
                 : "r"((a)[0]), "r"((a)[1]), "r"((a)[2]), "r"((a)[3]),       \
                   "r"(b0), "r"(b1))
#define MMA16816H(d, a, b0, b1)                                              \
    asm volatile("mma.sync.aligned.m16n8k16.row.col.f32.f16.f16.f32 "        \
                 "{%0,%1,%2,%3}, {%4,%5,%6,%7}, {%8,%9}, {%0,%1,%2,%3};"     \
                 : "+f"((d)[0]), "+f"((d)[1]), "+f"((d)[2]), "+f"((d)[3])    \
                 : "r"((a)[0]), "r"((a)[1]), "r"((a)[2]), "r"((a)[3]),       \
                   "r"(b0), "r"(b1))
#define CP_ASYNC16(dst, src)                                                 \
    asm volatile("cp.async.cg.shared.global [%0], [%1], 16;"                 \
                 :: "r"(dst), "l"(src))
#define CP_COMMIT() asm volatile("cp.async.commit_group;" ::: "memory")
#define CP_WAIT(n)  asm volatile("cp.async.wait_group %0;" :: "n"(n) : "memory")
#define STS32(addr, v)                                                       \
    asm volatile("st.shared.u32 [%0], %1;" :: "r"(addr), "r"(v) : "memory")

union BU { __nv_bfloat162 b; uint32_t u; };
union HU { __half2 h; uint32_t u; };
__device__ __forceinline__ uint32_t pack_hi2(float x, float y) {
    BU t; t.b = __floats2bfloat162_rn(x, y); return t.u;
}
__device__ __forceinline__ uint32_t pack_lo2(float x, float y) {
    float rx = x - __bfloat162float(__float2bfloat16(x));
    float ry = y - __bfloat162float(__float2bfloat16(y));
    BU t; t.b = __floats2bfloat162_rn(rx, ry); return t.u;
}
__device__ __forceinline__ uint32_t pack_h2(float x, float y) {
    HU t; t.h = __floats2half2_rn(x, y); return t.u;
}
__device__ __forceinline__ float ex2(float x) {
    float y; asm("ex2.approx.ftz.f32 %0, %1;" : "=f"(y) : "f"(x)); return y;
}

// ---------------------------------------------------------------------------
// split fp32 -> bf16 hi + lo. which=0 -> (g_ahi,g_alo); which=1 -> (g_bhi,g_blo)
// ---------------------------------------------------------------------------
__global__ __launch_bounds__(256) void split_kernel(const float* __restrict__ src,
                                                    int which, int n)
{
    int i = (blockIdx.x * 256 + threadIdx.x) * 8;
    if (i >= n) return;
    __nv_bfloat16* hi = which ? g_bhi : g_ahi;
    __nv_bfloat16* lo = which ? g_blo : g_alo;
    float4 a = *(const float4*)(src + i);
    float4 b = *(const float4*)(src + i + 4);
    uint4 hv, lv;
    hv.x = pack_hi2(a.x, a.y);  hv.y = pack_hi2(a.z, a.w);
    hv.z = pack_hi2(b.x, b.y);  hv.w = pack_hi2(b.z, b.w);
    lv.x = pack_lo2(a.x, a.y);  lv.y = pack_lo2(a.z, a.w);
    lv.z = pack_lo2(b.x, b.y);  lv.w = pack_lo2(b.z, b.w);
    *(uint4*)(hi + i) = hv;
    *(uint4*)(lo + i) = lv;
}

// ---------------------------------------------------------------------------
// mma.sync bf16x3 GEMM (NT). mode 0: C[m*ldc+n]. mode 1: scatter fp16 q/v.
// ---------------------------------------------------------------------------
#define KDIM   1024
#define SROW   40
#define ABYTES (128 * SROW * 2)
#define STAGEB (4 * ABYTES)
#define GEMM_SMEM (2 * STAGEB)

__global__ __launch_bounds__(256, 1) void mma_gemm(float* __restrict__ C,
                                                   int ldc, int mode)
{
    extern __shared__ char smem[];
    const uint32_t sbase = smem_u32(smem);

    const int tid  = threadIdx.x;
    const int warp = tid >> 5;
    const int lane = tid & 31;
    const int wm   = warp & 1;
    const int wn   = warp >> 1;

    const int m0 = blockIdx.y * 128;
    const int n0 = blockIdx.x * 128;

    const int lrow  = tid >> 1;
    const int lhalf = (tid & 1) * 16;
    const __nv_bfloat16* pAh = g_ahi + (size_t)(m0 + lrow) * KDIM + lhalf;
    const __nv_bfloat16* pAl = g_alo + (size_t)(m0 + lrow) * KDIM + lhalf;
    const __nv_bfloat16* pBh = g_bhi + (size_t)(n0 + lrow) * KDIM + lhalf;
    const __nv_bfloat16* pBl = g_blo + (size_t)(n0 + lrow) * KDIM + lhalf;
    const uint32_t so = (uint32_t)(lrow * SROW + lhalf) * 2;

    const int fr = (lane & 7) + ((lane >> 3) & 1) * 8;
    const int fc = (lane >> 4) * 8;

    float acc[4][4][4];
#pragma unroll
    for (int i = 0; i < 4; i++)
#pragma unroll
        for (int j = 0; j < 4; j++)
#pragma unroll
            for (int c = 0; c < 4; c++) acc[i][j][c] = 0.0f;

#define ISSUE(ch) do {                                                       \
        const uint32_t st = sbase + ((ch) & 1) * STAGEB + so;                \
        const int ko = (ch) * 32;                                            \
        CP_ASYNC16(st,                  pAh + ko);                           \
        CP_ASYNC16(st + 16,             pAh + ko + 8);                       \
        CP_ASYNC16(st + ABYTES,         pAl + ko);                           \
        CP_ASYNC16(st + ABYTES + 16,    pAl + ko + 8);                       \
        CP_ASYNC16(st + 2 * ABYTES,      pBh + ko);                          \
        CP_ASYNC16(st + 2 * ABYTES + 16, pBh + ko + 8);                      \
        CP_ASYNC16(st + 3 * ABYTES,      pBl + ko);                          \
        CP_ASYNC16(st + 3 * ABYTES + 16, pBl + ko + 8);                      \
        CP_COMMIT();                                                         \
    } while (0)

    ISSUE(0);

    for (int ch = 0; ch < KDIM / 32; ch++) {
        if (ch + 1 < KDIM / 32) { ISSUE(ch + 1); CP_WAIT(1); }
        else                    { CP_WAIT(0); }
        __syncthreads();

        const char* stg = smem + (ch & 1) * STAGEB;
        const __nv_bfloat16* sAh = (const __nv_bfloat16*)(stg);
        const __nv_bfloat16* sAl = (const __nv_bfloat16*)(stg + ABYTES);
        const __nv_bfloat16* sBh = (const __nv_bfloat16*)(stg + 2 * ABYTES);
        const __nv_bfloat16* sBl = (const __nv_bfloat16*)(stg + 3 * ABYTES);

#pragma unroll
        for (int ks = 0; ks < 2; ks++) {
            const int kc = ks * 16 + fc;
            uint32_t bh[2][4], bl[2][4];
#pragma unroll
            for (int np = 0; np < 2; np++) {
                const int row = wn * 32 + np * 16 + fr;
                LDSM_X4(bh[np][0], bh[np][1], bh[np][2], bh[np][3],
                        smem_u32(sBh + row * SROW + kc));
                LDSM_X4(bl[np][0], bl[np][1], bl[np][2], bl[np][3],
                        smem_u32(sBl + row * SROW + kc));
            }
#pragma unroll
            for (int mt = 0; mt < 4; mt++) {
                const int row = wm * 64 + mt * 16 + fr;
                uint32_t ah[4], al[4];
                LDSM_X4(ah[0], ah[1], ah[2], ah[3],
                        smem_u32(sAh + row * SROW + kc));
                LDSM_X4(al[0], al[1], al[2], al[3],
                        smem_u32(sAl + row * SROW + kc));
#pragma unroll
                for (int nt = 0; nt < 4; nt++) {
                    const int np = nt >> 1, sub = nt & 1;
                    const uint32_t b0h = bh[np][sub], b1h = bh[np][sub + 2];
                    const uint32_t b0l = bl[np][sub], b1l = bl[np][sub + 2];
                    MMA16816(acc[mt][nt], ah, b0h, b1h);
                    MMA16816(acc[mt][nt], ah, b0l, b1l);
                    MMA16816(acc[mt][nt], al, b0h, b1h);
                }
            }
        }
        __syncthreads();
    }

    const int r0 = lane >> 2;
    const int c0 = (lane & 3) * 2;
#pragma unroll
    for (int mt = 0; mt < 4; mt++) {
#pragma unroll
        for (int half = 0; half < 2; half++) {
            const int m = m0 + wm * 64 + mt * 16 + r0 + half * 8;
#pragma unroll
            for (int nt = 0; nt < 4; nt++) {
                const int e = n0 + wn * 32 + nt * 8 + c0;
                float vx = acc[mt][nt][half * 2 + 0];
                float vy = acc[mt][nt][half * 2 + 1];
                if (mode == 0) {
                    float2 v; v.x = vx; v.y = vy;
                    *(float2*)(C + (size_t)m * ldc + e) = v;
                } else {
                    const int bb = m >> 11, nn = m & 2047;
                    if (e < DIMV) {
                        const int hh = e >> 6, d0 = e & 63;
                        size_t idx = (((size_t)(bb * HEADS + hh)) * NSEQ + nn) * DH + d0;
                        *(uint32_t*)(g_q16 + idx) = pack_h2(vx, vy);
                    } else {
                        const int e2 = e - DIMV;
                        const int hh = e2 >> 6, d0 = e2 & 63;
                        size_t bs = ((size_t)(bb * HEADS + hh)) * DH;
                        g_v16[(bs + d0)     * NSEQ + nn] = __float2half(vx);
                        g_v16[(bs + d0 + 1) * NSEQ + nn] = __float2half(vy);
                    }
                }
            }
        }
    }
}

// ---------------------------------------------------------------------------
// ||q||^2 per row from the fp16-rounded q (consistent with fp16 QK mma)
// ---------------------------------------------------------------------------
__global__ __launch_bounds__(256) void sq_kernel()
{
    int row = blockIdx.x * blockDim.x + threadIdx.x;
    if (row >= BATCH * HEADS * NSEQ) return;
    const __half2* p = (const __half2*)(g_q16 + (size_t)row * DH);
    float s = 0.0f;
#pragma unroll
    for (int i = 0; i < 32; i++) {
        float2 f = __half22float2(p[i]);
        s += f.x * f.x + f.y * f.y;
    }
    g_sq[row] = s;
}

// ---------------------------------------------------------------------------
// fp16 mma.sync L2 attention: S = Q16·K16, P fp16, PV = P16·V16.
// Analytic max 0 (sq from rounded q); l summed from rounded fp16 P.
// 64 MMAs/warp/tile. smem 73.5KB, 2 CTAs/SM.
// ---------------------------------------------------------------------------
#define A_SQ   0                     // Q: 128*144 = 18432
#define A_ST0  18432                 // stages: 2 x 18688
#define A_STSZ 18688
#define A_K    0
#define A_V    9216
#define A_SQS  18432
#define A_PH   55808                 // 128*144 = 18432
#define A_L2D  74240                 // 256 floats
#define ATT_SMEM 75264

__global__ __launch_bounds__(256, 2) void mma_attn()
{
    extern __shared__ char sm[];
    const uint32_t sb = smem_u32(sm);
    const int tid  = threadIdx.x;
    const int warp = tid >> 5;
    const int lane = tid & 31;
    const int wm   = warp & 3;    // 4 m-groups of 32 q-rows
    const int wn   = warp >> 2;   // 2 n-groups (keys / dh halves)
    const int qb = blockIdx.x, h = blockIdx.y, b = blockIdx.z;
    const int bh = b * HEADS + h;

    const __half* Qg = g_q16 + (size_t)bh * NSEQ * DH;
    const __half* Vg = g_v16 + (size_t)bh * DH * NSEQ;
    const float* sqg = g_sq + (size_t)bh * NSEQ;

    const int fr = (lane & 7) + ((lane >> 3) & 1) * 8;
    const int fc = (lane >> 4) * 8;
    const int r4 = lane >> 2;
    const int c2 = (lane & 3) * 2;

    const float C = 0.18033688011112042f;  // log2(e)/8

    float sqnC[2][2];
#pragma unroll
    for (int mt = 0; mt < 2; mt++) {
        sqnC[mt][0] = sqg[qb * 128 + wm * 32 + mt * 16 + r4]     * C;
        sqnC[mt][1] = sqg[qb * 128 + wm * 32 + mt * 16 + r4 + 8] * C;
    }

    // issue Q tile (rows qb*128..; 144B smem stride)
    for (int s = tid; s < 128 * 8; s += 256) {
        int row = s >> 3, seg = s & 7;
        CP_ASYNC16(sb + A_SQ + row * 144 + seg * 16,
                   Qg + (size_t)(qb * 128 + row) * DH + seg * 8);
    }

    auto issue_tile = [&](int t) {
        const uint32_t stb = sb + A_ST0 + (t & 1) * A_STSZ;
        for (int s = tid; s < 64 * 8; s += 256) {
            int row = s >> 3, seg = s & 7;
            CP_ASYNC16(stb + A_K + row * 144 + seg * 16,
                       Qg + (size_t)(t * 64 + row) * DH + seg * 8);
            CP_ASYNC16(stb + A_V + row * 144 + seg * 16,
                       Vg + (size_t)row * NSEQ + t * 64 + seg * 8);
        }
        if (tid < 16)
            CP_ASYNC16(stb + A_SQS + tid * 16, sqg + t * 64 + tid * 4);
        CP_COMMIT();
    };

    issue_tile(0);  // commits Q too

    float acc[2][4][4];
#pragma unroll
    for (int i = 0; i < 2; i++)
#pragma unroll
        for (int j = 0; j < 4; j++)
#pragma unroll
            for (int c = 0; c < 4; c++) acc[i][j][c] = 0.0f;
    float lacc[2][2] = {{0.f, 0.f}, {0.f, 0.f}};

    for (int t = 0; t < NSEQ / 64; t++) {
        if (t + 1 < NSEQ / 64) { issue_tile(t + 1); CP_WAIT(1); }
        else                   { CP_WAIT(0); }
        __syncthreads();

        const uint32_t kb = sb + A_ST0 + (t & 1) * A_STSZ;
        const float* sqs = (const float*)(sm + A_ST0 + (t & 1) * A_STSZ + A_SQS);

        // ---- QK: S = Q16 x K16 --------------------------------------------
        float S[2][4][4];
#pragma unroll
        for (int i = 0; i < 2; i++)
#pragma unroll
            for (int j = 0; j < 4; j++)
#pragma unroll
                for (int c = 0; c < 4; c++) S[i][j][c] = 0.0f;

#pragma unroll
        for (int kc = 0; kc < 4; kc++) {
            const int colb = (kc * 16 + fc) * 2;
            uint32_t kf[2][4];
#pragma unroll
            for (int np = 0; np < 2; np++) {
                const int row = wn * 32 + np * 16 + fr;
                LDSM_X4(kf[np][0], kf[np][1], kf[np][2], kf[np][3],
                        kb + A_K + row * 144 + colb);
            }
#pragma unroll
            for (int mt = 0; mt < 2; mt++) {
                const int arow = wm * 32 + mt * 16 + fr;
                uint32_t ah[4];
                LDSM_X4(ah[0], ah[1], ah[2], ah[3], sb + A_SQ + arow * 144 + colb);
#pragma unroll
                for (int nt = 0; nt < 4; nt++) {
                    const int np = nt >> 1, sub = nt & 1;
                    MMA16816H(S[mt][nt], ah, kf[np][sub], kf[np][sub + 2]);
                }
            }
        }

        // ---- softmax (analytic max 0), pack fp16 P, l from ROUNDED P ------
#pragma unroll
        for (int mt = 0; mt < 2; mt++) {
#pragma unroll
            for (int nt = 0; nt < 4; nt++) {
                const int col = wn * 32 + nt * 8 + c2;
                const float sqm0 = sqs[col], sqm1 = sqs[col + 1];
                float p0 = ex2(fmaf(fmaf(2.f, S[mt][nt][0], -sqm0), C, -sqnC[mt][0]));
                float p1 = ex2(fmaf(fmaf(2.f, S[mt][nt][1], -sqm1), C, -sqnC[mt][0]));
                float p2 = ex2(fmaf(fmaf(2.f, S[mt][nt][2], -sqm0), C, -sqnC[mt][1]));
                float p3 = ex2(fmaf(fmaf(2.f, S[mt][nt][3], -sqm1), C, -sqnC[mt][1]));
                HU u01; u01.h = __floats2half2_rn(p0, p1);
                HU u23; u23.h = __floats2half2_rn(p2, p3);
                float2 f01 = __half22float2(u01.h);
                float2 f23 = __half22float2(u23.h);
                lacc[mt][0] += f01.x + f01.y;
                lacc[mt][1] += f23.x + f23.y;
                const int row = wm * 32 + mt * 16 + r4;
                const uint32_t cb = col * 2;
                STS32(sb + A_PH + row * 144 + cb,       u01.u);
                STS32(sb + A_PH + (row + 8) * 144 + cb, u23.u);
            }
        }
        __syncthreads();

        // ---- PV: out += P16 x V16 -----------------------------------------
#pragma unroll
        for (int kc = 0; kc < 4; kc++) {
            const int colb = (kc * 16 + fc) * 2;
            uint32_t vf[2][4];
#pragma unroll
            for (int np = 0; np < 2; np++) {
                const int row = wn * 32 + np * 16 + fr;
                LDSM_X4(vf[np][0], vf[np][1], vf[np][2], vf[np][3],
                        kb + A_V + row * 144 + colb);
            }
#pragma unroll
            for (int mt = 0; mt < 2; mt++) {
                const int arow = wm * 32 + mt * 16 + fr;
                uint32_t ph[4];
                LDSM_X4(ph[0], ph[1], ph[2], ph[3], sb + A_PH + arow * 144 + colb);
#pragma unroll
                for (int nt = 0; nt < 4; nt++) {
                    const int np = nt >> 1, sub = nt & 1;
                    MMA16816H(acc[mt][nt], ph, vf[np][sub], vf[np][sub + 2]);
                }
            }
        }
        __syncthreads();  // stage/P reuse protection
    }

    // ---- l reduction across quads and the two wn warps ---------------------
    float* l2d = (float*)(sm + A_L2D);
#pragma unroll
    for (int mt = 0; mt < 2; mt++)
#pragma unroll
        for (int hf = 0; hf < 2; hf++) {
            float l = lacc[mt][hf];
            l += __shfl_xor_sync(0xffffffffu, l, 1);
            l += __shfl_xor_sync(0xffffffffu, l, 2);
            if ((lane & 3) == 0)
                l2d[wn * 128 + wm * 32 + mt * 16 + hf * 8 + r4] = l;
        }
    __syncthreads();

    // ---- epilogue: normalize, split to bf16 hi/lo, write to gemm-A ---------
#pragma unroll
    for (int mt = 0; mt < 2; mt++) {
#pragma unroll
        for (int hf = 0; hf < 2; hf++) {
            const int row = wm * 32 + mt * 16 + hf * 8 + r4;
            const float linv = 1.0f / (l2d[row] + l2d[128 + row]);
            const int n = qb * 128 + row;
#pragma unroll
            for (int nt = 0; nt < 4; nt++) {
                const int dcol = h * DH + wn * 32 + nt * 8 + c2;
                const float vx = acc[mt][nt][hf * 2 + 0] * linv;
                const float vy = acc[mt][nt][hf * 2 + 1] * linv;
                size_t idx = ((size_t)b * NSEQ + n) * DIMV + dcol;
                *(uint32_t*)(g_ahi + idx) = pack_hi2(vx, vy);
                *(uint32_t*)(g_alo + idx) = pack_lo2(vx, vy);
            }
        }
    }
}

// ---------------------------------------------------------------------------

extern "C" void kernel_launch(void* const* d_in, const int* in_sizes, int n_in,
                              void* d_out, int out_size)
{
    const float* x    = (const float*)d_in[0];   // [2,2048,1024]
    const float* w_qv = (const float*)d_in[1];   // [2048,1024]
    const float* w_o  = (const float*)d_in[2];   // [1024,1024]
    float* out = (float*)d_out;                  // [2,2048,1024]

    cudaFuncSetAttribute(mma_gemm, cudaFuncAttributeMaxDynamicSharedMemorySize,
                         GEMM_SMEM);
    cudaFuncSetAttribute(mma_attn, cudaFuncAttributeMaxDynamicSharedMemorySize,
                         ATT_SMEM);

    // 1) split x -> A pair, w_qv -> B pair
    split_kernel<<<4096 * 1024 / 8 / 256, 256>>>(x, 0, 4096 * 1024);
    split_kernel<<<2048 * 1024 / 8 / 256, 256>>>(w_qv, 1, 2048 * 1024);

    // 2) QV projection -> fp16 q (row-major) / v (transposed)
    mma_gemm<<<dim3(16, 32), 256, GEMM_SMEM>>>(nullptr, 0, 1);

    // 3) split w_o -> B pair; ||q||^2 (from fp16 q)
    split_kernel<<<1024 * 1024 / 8 / 256, 256>>>(w_o, 1, 1024 * 1024);
    sq_kernel<<<(BATCH * HEADS * NSEQ) / 256, 256>>>();

    // 4) fp16 tensor-core attention -> writes split output into A pair
    mma_attn<<<dim3(NSEQ / 128, HEADS, BATCH), 256, ATT_SMEM>>>();

    // 5) Wo projection -> out
    mma_gemm<<<dim3(8, 32), 256, GEMM_SMEM>>>(out, 1024, 0);
}

// round 15
// speedup vs baseline: 5.1157x; 1.3149x over previous
// R14: verbatim resubmission of R13 — round 14 died at GB300 container
//      acquisition (infra); kernel never compiled/ran. fp16 single-pass QV
//      GEMM + fp16 attention + bf16x3 Wo GEMM. See R13 header for rationale.
#include <cuda_runtime.h>
#include <cuda_bf16.h>
#include <cuda_fp16.h>
#include <cstdint>

#define BATCH 2
#define NSEQ  2048
#define DIMV  1024
#define HEADS 16
#define DH    64

// ---------------- scratch (device globals; total 44.25 MB) ------------------
__device__ float g_sq[BATCH * HEADS * NSEQ];                    // 0.25 MB
__device__ __half g_x16[4096 * 1024];                           // 8 MB  x fp16
__device__ __half g_w16[2048 * 1024];                           // 4 MB  w_qv fp16
__device__ __half g_q16[BATCH * HEADS * NSEQ * DH];             // 8 MB [bh][n][d]
__device__ __half g_v16[BATCH * HEADS * DH * NSEQ];             // 8 MB [bh][d][n]
__device__ __nv_bfloat16 g_ahi[4096 * 1024];                    // 8 MB  Wo A hi
__device__ __nv_bfloat16 g_alo[4096 * 1024];                    // 8 MB  Wo A lo
__device__ __nv_bfloat16 g_bhi[1024 * 1024];                    // 2 MB  Wo B hi
__device__ __nv_bfloat16 g_blo[1024 * 1024];                    // 2 MB  Wo B lo

// ---------------- helpers ---------------------------------------------------
__device__ __forceinline__ uint32_t smem_u32(const void* p) {
    uint32_t a;
    asm("{ .reg .u64 t; cvta.to.shared.u64 t, %1; cvt.u32.u64 %0, t; }"
        : "=r"(a) : "l"(p));
    return a;
}
#define LDSM_X4(r0, r1, r2, r3, addr)                                        \
    asm volatile("ldmatrix.sync.aligned.m8n8.x4.shared.b16 {%0,%1,%2,%3}, [%4];" \
                 : "=r"(r0), "=r"(r1), "=r"(r2), "=r"(r3) : "r"(addr))
#define MMA16816(d, a, b0, b1)                                               \
    asm volatile("mma.sync.aligned.m16n8k16.row.col.f32.bf16.bf16.f32 "      \
                 "{%0,%1,%2,%3}, {%4,%5,%6,%7}, {%8,%9}, {%0,%1,%2,%3};"     \
                 : "+f"((d)[0]), "+f"((d)[1]), "+f"((d)[2]), "+f"((d)[3])    \
                 : "r"((a)[0]), "r"((a)[1]), "r"((a)[2]), "r"((a)[3]),       \
                   "r"(b0), "r"(b1))
#define MMA16816H(d, a, b0, b1)                                              \
    asm volatile("mma.sync.aligned.m16n8k16.row.col.f32.f16.f16.f32 "        \
                 "{%0,%1,%2,%3}, {%4,%5,%6,%7}, {%8,%9}, {%0,%1,%2,%3};"     \
                 : "+f"((d)[0]), "+f"((d)[1]), "+f"((d)[2]), "+f"((d)[3])    \
                 : "r"((a)[0]), "r"((a)[1]), "r"((a)[2]), "r"((a)[3]),       \
                   "r"(b0), "r"(b1))
#define CP_ASYNC16(dst, src)                                                 \
    asm volatile("cp.async.cg.shared.global [%0], [%1], 16;"                 \
                 :: "r"(dst), "l"(src))
#define CP_COMMIT() asm volatile("cp.async.commit_group;" ::: "memory")
#define CP_WAIT(n)  asm volatile("cp.async.wait_group %0;" :: "n"(n) : "memory")
#define STS32(addr, v)                                                       \
    asm volatile("st.shared.u32 [%0], %1;" :: "r"(addr), "r"(v) : "memory")

union BU { __nv_bfloat162 b; uint32_t u; };
union HU { __half2 h; uint32_t u; };
__device__ __forceinline__ uint32_t pack_hi2(float x, float y) {
    BU t; t.b = __floats2bfloat162_rn(x, y); return t.u;
}
__device__ __forceinline__ uint32_t pack_lo2(float x, float y) {
    float rx = x - __bfloat162float(__float2bfloat16(x));
    float ry = y - __bfloat162float(__float2bfloat16(y));
    BU t; t.b = __floats2bfloat162_rn(rx, ry); return t.u;
}
__device__ __forceinline__ uint32_t pack_h2(float x, float y) {
    HU t; t.h = __floats2half2_rn(x, y); return t.u;
}
__device__ __forceinline__ float ex2(float x) {
    float y; asm("ex2.approx.ftz.f32 %0, %1;" : "=f"(y) : "f"(x)); return y;
}

// ---------------------------------------------------------------------------
// convert fp32 -> fp16. which=0 -> g_x16, which=1 -> g_w16
// ---------------------------------------------------------------------------
__global__ __launch_bounds__(256) void conv16_kernel(const float* __restrict__ src,
                                                     int which, int n)
{
    int i = (blockIdx.x * 256 + threadIdx.x) * 8;
    if (i >= n) return;
    __half* dst = which ? g_w16 : g_x16;
    float4 a = *(const float4*)(src + i);
    float4 b = *(const float4*)(src + i + 4);
    uint4 hv;
    hv.x = pack_h2(a.x, a.y);  hv.y = pack_h2(a.z, a.w);
    hv.z = pack_h2(b.x, b.y);  hv.w = pack_h2(b.z, b.w);
    *(uint4*)(dst + i) = hv;
}

// ---------------------------------------------------------------------------
// split fp32 -> bf16 hi + lo into (g_bhi, g_blo)  [w_o only]
// ---------------------------------------------------------------------------
__global__ __launch_bounds__(256) void split_kernel(const float* __restrict__ src,
                                                    int n)
{
    int i = (blockIdx.x * 256 + threadIdx.x) * 8;
    if (i >= n) return;
    float4 a = *(const float4*)(src + i);
    float4 b = *(const float4*)(src + i + 4);
    uint4 hv, lv;
    hv.x = pack_hi2(a.x, a.y);  hv.y = pack_hi2(a.z, a.w);
    hv.z = pack_hi2(b.x, b.y);  hv.w = pack_hi2(b.z, b.w);
    lv.x = pack_lo2(a.x, a.y);  lv.y = pack_lo2(a.z, a.w);
    lv.z = pack_lo2(b.x, b.y);  lv.w = pack_lo2(b.z, b.w);
    *(uint4*)(g_bhi + i) = hv;
    *(uint4*)(g_blo + i) = lv;
}

#define KDIM   1024
#define SROW   40
#define ABYTES (128 * SROW * 2)     // 10240 per operand tile

// ---------------------------------------------------------------------------
// fp16 single-pass QV GEMM (NT): qv = x16 @ w16^T, scatter q/v epilogue.
// Block 128x128, BK=32, 8 warps, 2-stage cp.async. grid (16, 32).
// ---------------------------------------------------------------------------
#define STAGEB16 (2 * ABYTES)       // 20480 per stage
#define GEMM16_SMEM (2 * STAGEB16)  // 40960

__global__ __launch_bounds__(256, 2) void mma_gemm16()
{
    extern __shared__ char smem[];
    const uint32_t sbase = smem_u32(smem);

    const int tid  = threadIdx.x;
    const int warp = tid >> 5;
    const int lane = tid & 31;
    const int wm   = warp & 1;
    const int wn   = warp >> 1;

    const int m0 = blockIdx.y * 128;
    const int n0 = blockIdx.x * 128;

    const int lrow  = tid >> 1;
    const int lhalf = (tid & 1) * 16;
    const __half* pA = g_x16 + (size_t)(m0 + lrow) * KDIM + lhalf;
    const __half* pB = g_w16 + (size_t)(n0 + lrow) * KDIM + lhalf;
    const uint32_t so = (uint32_t)(lrow * SROW + lhalf) * 2;

    const int fr = (lane & 7) + ((lane >> 3) & 1) * 8;
    const int fc = (lane >> 4) * 8;

    float acc[4][4][4];
#pragma unroll
    for (int i = 0; i < 4; i++)
#pragma unroll
        for (int j = 0; j < 4; j++)
#pragma unroll
            for (int c = 0; c < 4; c++) acc[i][j][c] = 0.0f;

#define ISSUE16(ch) do {                                                     \
        const uint32_t st = sbase + ((ch) & 1) * STAGEB16 + so;              \
        const int ko = (ch) * 32;                                            \
        CP_ASYNC16(st,               pA + ko);                               \
        CP_ASYNC16(st + 16,          pA + ko + 8);                           \
        CP_ASYNC16(st + ABYTES,      pB + ko);                               \
        CP_ASYNC16(st + ABYTES + 16, pB + ko + 8);                           \
        CP_COMMIT();                                                         \
    } while (0)

    ISSUE16(0);

    for (int ch = 0; ch < KDIM / 32; ch++) {
        if (ch + 1 < KDIM / 32) { ISSUE16(ch + 1); CP_WAIT(1); }
        else                    { CP_WAIT(0); }
        __syncthreads();

        const char* stg = smem + (ch & 1) * STAGEB16;
        const __half* sA = (const __half*)(stg);
        const __half* sB = (const __half*)(stg + ABYTES);

#pragma unroll
        for (int ks = 0; ks < 2; ks++) {
            const int kc = ks * 16 + fc;
            uint32_t bf[2][4];
#pragma unroll
            for (int np = 0; np < 2; np++) {
                const int row = wn * 32 + np * 16 + fr;
                LDSM_X4(bf[np][0], bf[np][1], bf[np][2], bf[np][3],
                        smem_u32(sB + row * SROW + kc));
            }
#pragma unroll
            for (int mt = 0; mt < 4; mt++) {
                const int row = wm * 64 + mt * 16 + fr;
                uint32_t af[4];
                LDSM_X4(af[0], af[1], af[2], af[3],
                        smem_u32(sA + row * SROW + kc));
#pragma unroll
                for (int nt = 0; nt < 4; nt++) {
                    const int np = nt >> 1, sub = nt & 1;
                    MMA16816H(acc[mt][nt], af, bf[np][sub], bf[np][sub + 2]);
                }
            }
        }
        __syncthreads();
    }

    // scatter epilogue: q fp16 row-major, v fp16 transposed
    const int r0 = lane >> 2;
    const int c0 = (lane & 3) * 2;
#pragma unroll
    for (int mt = 0; mt < 4; mt++) {
#pragma unroll
        for (int half = 0; half < 2; half++) {
            const int m = m0 + wm * 64 + mt * 16 + r0 + half * 8;
            const int bb = m >> 11, nn = m & 2047;
#pragma unroll
            for (int nt = 0; nt < 4; nt++) {
                const int e = n0 + wn * 32 + nt * 8 + c0;
                float vx = acc[mt][nt][half * 2 + 0];
                float vy = acc[mt][nt][half * 2 + 1];
                if (e < DIMV) {
                    const int hh = e >> 6, d0 = e & 63;
                    size_t idx = (((size_t)(bb * HEADS + hh)) * NSEQ + nn) * DH + d0;
                    *(uint32_t*)(g_q16 + idx) = pack_h2(vx, vy);
                } else {
                    const int e2 = e - DIMV;
                    const int hh = e2 >> 6, d0 = e2 & 63;
                    size_t bs = ((size_t)(bb * HEADS + hh)) * DH;
                    g_v16[(bs + d0)     * NSEQ + nn] = __float2half(vx);
                    g_v16[(bs + d0 + 1) * NSEQ + nn] = __float2half(vy);
                }
            }
        }
    }
}

// ---------------------------------------------------------------------------
// bf16x3 Wo GEMM (NT): out = A(g_ahi/g_alo) @ B(g_bhi/g_blo)^T. grid (8, 32).
// ---------------------------------------------------------------------------
#define STAGEB (4 * ABYTES)
#define GEMM_SMEM (2 * STAGEB)

__global__ __launch_bounds__(256, 1) void mma_gemm3(float* __restrict__ C, int ldc)
{
    extern __shared__ char smem[];
    const uint32_t sbase = smem_u32(smem);

    const int tid  = threadIdx.x;
    const int warp = tid >> 5;
    const int lane = tid & 31;
    const int wm   = warp & 1;
    const int wn   = warp >> 1;

    const int m0 = blockIdx.y * 128;
    const int n0 = blockIdx.x * 128;

    const int lrow  = tid >> 1;
    const int lhalf = (tid & 1) * 16;
    const __nv_bfloat16* pAh = g_ahi + (size_t)(m0 + lrow) * KDIM + lhalf;
    const __nv_bfloat16* pAl = g_alo + (size_t)(m0 + lrow) * KDIM + lhalf;
    const __nv_bfloat16* pBh = g_bhi + (size_t)(n0 + lrow) * KDIM + lhalf;
    const __nv_bfloat16* pBl = g_blo + (size_t)(n0 + lrow) * KDIM + lhalf;
    const uint32_t so = (uint32_t)(lrow * SROW + lhalf) * 2;

    const int fr = (lane & 7) + ((lane >> 3) & 1) * 8;
    const int fc = (lane >> 4) * 8;

    float acc[4][4][4];
#pragma unroll
    for (int i = 0; i < 4; i++)
#pragma unroll
        for (int j = 0; j < 4; j++)
#pragma unroll
            for (int c = 0; c < 4; c++) acc[i][j][c] = 0.0f;

#define ISSUE(ch) do {                                                       \
        const uint32_t st = sbase + ((ch) & 1) * STAGEB + so;                \
        const int ko = (ch) * 32;                                            \
        CP_ASYNC16(st,                  pAh + ko);                           \
        CP_ASYNC16(st + 16,             pAh + ko + 8);                       \
        CP_ASYNC16(st + ABYTES,         pAl + ko);                           \
        CP_ASYNC16(st + ABYTES + 16,    pAl + ko + 8);                       \
        CP_ASYNC16(st + 2 * ABYTES,      pBh + ko);                          \
        CP_ASYNC16(st + 2 * ABYTES + 16, pBh + ko + 8);                      \
        CP_ASYNC16(st + 3 * ABYTES,      pBl + ko);                          \
        CP_ASYNC16(st + 3 * ABYTES + 16, pBl + ko + 8);                      \
        CP_COMMIT();                                                         \
    } while (0)

    ISSUE(0);

    for (int ch = 0; ch < KDIM / 32; ch++) {
        if (ch + 1 < KDIM / 32) { ISSUE(ch + 1); CP_WAIT(1); }
        else                    { CP_WAIT(0); }
        __syncthreads();

        const char* stg = smem + (ch & 1) * STAGEB;
        const __nv_bfloat16* sAh = (const __nv_bfloat16*)(stg);
        const __nv_bfloat16* sAl = (const __nv_bfloat16*)(stg + ABYTES);
        const __nv_bfloat16* sBh = (const __nv_bfloat16*)(stg + 2 * ABYTES);
        const __nv_bfloat16* sBl = (const __nv_bfloat16*)(stg + 3 * ABYTES);

#pragma unroll
        for (int ks = 0; ks < 2; ks++) {
            const int kc = ks * 16 + fc;
            uint32_t bh[2][4], bl[2][4];
#pragma unroll
            for (int np = 0; np < 2; np++) {
                const int row = wn * 32 + np * 16 + fr;
                LDSM_X4(bh[np][0], bh[np][1], bh[np][2], bh[np][3],
                        smem_u32(sBh + row * SROW + kc));
                LDSM_X4(bl[np][0], bl[np][1], bl[np][2], bl[np][3],
                        smem_u32(sBl + row * SROW + kc));
            }
#pragma unroll
            for (int mt = 0; mt < 4; mt++) {
                const int row = wm * 64 + mt * 16 + fr;
                uint32_t ah[4], al[4];
                LDSM_X4(ah[0], ah[1], ah[2], ah[3],
                        smem_u32(sAh + row * SROW + kc));
                LDSM_X4(al[0], al[1], al[2], al[3],
                        smem_u32(sAl + row * SROW + kc));
#pragma unroll
                for (int nt = 0; nt < 4; nt++) {
                    const int np = nt >> 1, sub = nt & 1;
                    const uint32_t b0h = bh[np][sub], b1h = bh[np][sub + 2];
                    const uint32_t b0l = bl[np][sub], b1l = bl[np][sub + 2];
                    MMA16816(acc[mt][nt], ah, b0h, b1h);
                    MMA16816(acc[mt][nt], ah, b0l, b1l);
                    MMA16816(acc[mt][nt], al, b0h, b1h);
                }
            }
        }
        __syncthreads();
    }

    const int r0 = lane >> 2;
    const int c0 = (lane & 3) * 2;
#pragma unroll
    for (int mt = 0; mt < 4; mt++) {
#pragma unroll
        for (int half = 0; half < 2; half++) {
            const int m = m0 + wm * 64 + mt * 16 + r0 + half * 8;
#pragma unroll
            for (int nt = 0; nt < 4; nt++) {
                const int e = n0 + wn * 32 + nt * 8 + c0;
                float2 v;
                v.x = acc[mt][nt][half * 2 + 0];
                v.y = acc[mt][nt][half * 2 + 1];
                *(float2*)(C + (size_t)m * ldc + e) = v;
            }
        }
    }
}

// ---------------------------------------------------------------------------
// ||q||^2 per row from the fp16-rounded q (consistent with fp16 QK mma)
// ---------------------------------------------------------------------------
__global__ __launch_bounds__(256) void sq_kernel()
{
    int row = blockIdx.x * blockDim.x + threadIdx.x;
    if (row >= BATCH * HEADS * NSEQ) return;
    const __half2* p = (const __half2*)(g_q16 + (size_t)row * DH);
    float s = 0.0f;
#pragma unroll
    for (int i = 0; i < 32; i++) {
        float2 f = __half22float2(p[i]);
        s += f.x * f.x + f.y * f.y;
    }
    g_sq[row] = s;
}

// ---------------------------------------------------------------------------
// fp16 mma.sync L2 attention (unchanged from R12).
// ---------------------------------------------------------------------------
#define A_SQ   0
#define A_ST0  18432
#define A_STSZ 18688
#define A_K    0
#define A_V    9216
#define A_SQS  18432
#define A_PH   55808
#define A_L2D  74240
#define ATT_SMEM 75264

__global__ __launch_bounds__(256, 2) void mma_attn()
{
    extern __shared__ char sm[];
    const uint32_t sb = smem_u32(sm);
    const int tid  = threadIdx.x;
    const int warp = tid >> 5;
    const int lane = tid & 31;
    const int wm   = warp & 3;
    const int wn   = warp >> 2;
    const int qb = blockIdx.x, h = blockIdx.y, b = blockIdx.z;
    const int bh = b * HEADS + h;

    const __half* Qg = g_q16 + (size_t)bh * NSEQ * DH;
    const __half* Vg = g_v16 + (size_t)bh * DH * NSEQ;
    const float* sqg = g_sq + (size_t)bh * NSEQ;

    const int fr = (lane & 7) + ((lane >> 3) & 1) * 8;
    const int fc = (lane >> 4) * 8;
    const int r4 = lane >> 2;
    const int c2 = (lane & 3) * 2;

    const float C = 0.18033688011112042f;  // log2(e)/8

    float sqnC[2][2];
#pragma unroll
    for (int mt = 0; mt < 2; mt++) {
        sqnC[mt][0] = sqg[qb * 128 + wm * 32 + mt * 16 + r4]     * C;
        sqnC[mt][1] = sqg[qb * 128 + wm * 32 + mt * 16 + r4 + 8] * C;
    }

    for (int s = tid; s < 128 * 8; s += 256) {
        int row = s >> 3, seg = s & 7;
        CP_ASYNC16(sb + A_SQ + row * 144 + seg * 16,
                   Qg + (size_t)(qb * 128 + row) * DH + seg * 8);
    }

    auto issue_tile = [&](int t) {
        const uint32_t stb = sb + A_ST0 + (t & 1) * A_STSZ;
        for (int s = tid; s < 64 * 8; s += 256) {
            int row = s >> 3, seg = s & 7;
            CP_ASYNC16(stb + A_K + row * 144 + seg * 16,
                       Qg + (size_t)(t * 64 + row) * DH + seg * 8);
            CP_ASYNC16(stb + A_V + row * 144 + seg * 16,
                       Vg + (size_t)row * NSEQ + t * 64 + seg * 8);
        }
        if (tid < 16)
            CP_ASYNC16(stb + A_SQS + tid * 16, sqg + t * 64 + tid * 4);
        CP_COMMIT();
    };

    issue_tile(0);

    float acc[2][4][4];
#pragma unroll
    for (int i = 0; i < 2; i++)
#pragma unroll
        for (int j = 0; j < 4; j++)
#pragma unroll
            for (int c = 0; c < 4; c++) acc[i][j][c] = 0.0f;
    float lacc[2][2] = {{0.f, 0.f}, {0.f, 0.f}};

    for (int t = 0; t < NSEQ / 64; t++) {
        if (t + 1 < NSEQ / 64) { issue_tile(t + 1); CP_WAIT(1); }
        else                   { CP_WAIT(0); }
        __syncthreads();

        const uint32_t kb = sb + A_ST0 + (t & 1) * A_STSZ;
        const float* sqs = (const float*)(sm + A_ST0 + (t & 1) * A_STSZ + A_SQS);

        float S[2][4][4];
#pragma unroll
        for (int i = 0; i < 2; i++)
#pragma unroll
            for (int j = 0; j < 4; j++)
#pragma unroll
                for (int c = 0; c < 4; c++) S[i][j][c] = 0.0f;

#pragma unroll
        for (int kc = 0; kc < 4; kc++) {
            const int colb = (kc * 16 + fc) * 2;
            uint32_t kf[2][4];
#pragma unroll
            for (int np = 0; np < 2; np++) {
                const int row = wn * 32 + np * 16 + fr;
                LDSM_X4(kf[np][0], kf[np][1], kf[np][2], kf[np][3],
                        kb + A_K + row * 144 + colb);
            }
#pragma unroll
            for (int mt = 0; mt < 2; mt++) {
                const int arow = wm * 32 + mt * 16 + fr;
                uint32_t ah[4];
                LDSM_X4(ah[0], ah[1], ah[2], ah[3], sb + A_SQ + arow * 144 + colb);
#pragma unroll
                for (int nt = 0; nt < 4; nt++) {
                    const int np = nt >> 1, sub = nt & 1;
                    MMA16816H(S[mt][nt], ah, kf[np][sub], kf[np][sub + 2]);
                }
            }
        }

#pragma unroll
        for (int mt = 0; mt < 2; mt++) {
#pragma unroll
            for (int nt = 0; nt < 4; nt++) {
                const int col = wn * 32 + nt * 8 + c2;
                const float sqm0 = sqs[col], sqm1 = sqs[col + 1];
                float p0 = ex2(fmaf(fmaf(2.f, S[mt][nt][0], -sqm0), C, -sqnC[mt][0]));
                float p1 = ex2(fmaf(fmaf(2.f, S[mt][nt][1], -sqm1), C, -sqnC[mt][0]));
                float p2 = ex2(fmaf(fmaf(2.f, S[mt][nt][2], -sqm0), C, -sqnC[mt][1]));
                float p3 = ex2(fmaf(fmaf(2.f, S[mt][nt][3], -sqm1), C, -sqnC[mt][1]));
                HU u01; u01.h = __floats2half2_rn(p0, p1);
                HU u23; u23.h = __floats2half2_rn(p2, p3);
                float2 f01 = __half22float2(u01.h);
                float2 f23 = __half22float2(u23.h);
                lacc[mt][0] += f01.x + f01.y;
                lacc[mt][1] += f23.x + f23.y;
                const int row = wm * 32 + mt * 16 + r4;
                const uint32_t cb = col * 2;
                STS32(sb + A_PH + row * 144 + cb,       u01.u);
                STS32(sb + A_PH + (row + 8) * 144 + cb, u23.u);
            }
        }
        __syncthreads();

#pragma unroll
        for (int kc = 0; kc < 4; kc++) {
            const int colb = (kc * 16 + fc) * 2;
            uint32_t vf[2][4];
#pragma unroll
            for (int np = 0; np < 2; np++) {
                const int row = wn * 32 + np * 16 + fr;
                LDSM_X4(vf[np][0], vf[np][1], vf[np][2], vf[np][3],
                        kb + A_V + row * 144 + colb);
            }
#pragma unroll
            for (int mt = 0; mt < 2; mt++) {
                const int arow = wm * 32 + mt * 16 + fr;
                uint32_t ph[4];
                LDSM_X4(ph[0], ph[1], ph[2], ph[3], sb + A_PH + arow * 144 + colb);
#pragma unroll
                for (int nt = 0; nt < 4; nt++) {
                    const int np = nt >> 1, sub = nt & 1;
                    MMA16816H(acc[mt][nt], ph, vf[np][sub], vf[np][sub + 2]);
                }
            }
        }
        __syncthreads();
    }

    float* l2d = (float*)(sm + A_L2D);
#pragma unroll
    for (int mt = 0; mt < 2; mt++)
#pragma unroll
        for (int hf = 0; hf < 2; hf++) {
            float l = lacc[mt][hf];
            l += __shfl_xor_sync(0xffffffffu, l, 1);
            l += __shfl_xor_sync(0xffffffffu, l, 2);
            if ((lane & 3) == 0)
                l2d[wn * 128 + wm * 32 + mt * 16 + hf * 8 + r4] = l;
        }
    __syncthreads();

#pragma unroll
    for (int mt = 0; mt < 2; mt++) {
#pragma unroll
        for (int hf = 0; hf < 2; hf++) {
            const int row = wm * 32 + mt * 16 + hf * 8 + r4;
            const float linv = 1.0f / (l2d[row] + l2d[128 + row]);
            const int n = qb * 128 + row;
#pragma unroll
            for (int nt = 0; nt < 4; nt++) {
                const int dcol = h * DH + wn * 32 + nt * 8 + c2;
                const float vx = acc[mt][nt][hf * 2 + 0] * linv;
                const float vy = acc[mt][nt][hf * 2 + 1] * linv;
                size_t idx = ((size_t)b * NSEQ + n) * DIMV + dcol;
                *(uint32_t*)(g_ahi + idx) = pack_hi2(vx, vy);
                *(uint32_t*)(g_alo + idx) = pack_lo2(vx, vy);
            }
        }
    }
}

// ---------------------------------------------------------------------------

extern "C" void kernel_launch(void* const* d_in, const int* in_sizes, int n_in,
                              void* d_out, int out_size)
{
    const float* x    = (const float*)d_in[0];   // [2,2048,1024]
    const float* w_qv = (const float*)d_in[1];   // [2048,1024]
    const float* w_o  = (const float*)d_in[2];   // [1024,1024]
    float* out = (float*)d_out;                  // [2,2048,1024]

    cudaFuncSetAttribute(mma_gemm16, cudaFuncAttributeMaxDynamicSharedMemorySize,
                         GEMM16_SMEM);
    cudaFuncSetAttribute(mma_gemm3, cudaFuncAttributeMaxDynamicSharedMemorySize,
                         GEMM_SMEM);
    cudaFuncSetAttribute(mma_attn, cudaFuncAttributeMaxDynamicSharedMemorySize,
                         ATT_SMEM);

    // 1) convert x, w_qv to fp16
    conv16_kernel<<<4096 * 1024 / 8 / 256, 256>>>(x, 0, 4096 * 1024);
    conv16_kernel<<<2048 * 1024 / 8 / 256, 256>>>(w_qv, 1, 2048 * 1024);

    // 2) fp16 QV projection -> q (row-major) / v (transposed)
    mma_gemm16<<<dim3(16, 32), 256, GEMM16_SMEM>>>();

    // 3) split w_o -> bf16 pair; ||q||^2 (from fp16 q)
    split_kernel<<<1024 * 1024 / 8 / 256, 256>>>(w_o, 1024 * 1024);
    sq_kernel<<<(BATCH * HEADS * NSEQ) / 256, 256>>>();

    // 4) fp16 tensor-core attention -> bf16 split output into A pair
    mma_attn<<<dim3(NSEQ / 128, HEADS, BATCH), 256, ATT_SMEM>>>();

    // 5) bf16x3 Wo projection -> out
    mma_gemm3<<<dim3(8, 32), 256, GEMM_SMEM>>>(out, 1024);
}

// round 17
// speedup vs baseline: 5.7176x; 1.1176x over previous
// R16: verbatim resubmission of R15 — round 16 died at GB300 container
//      acquisition (infra); kernel never compiled/ran. fp16x2 Wo GEMM +
//      fp16 QV GEMM + fp16 attention. See R15 header for rationale.
#include <cuda_runtime.h>
#include <cuda_bf16.h>
#include <cuda_fp16.h>
#include <cstdint>

#define BATCH 2
#define NSEQ  2048
#define DIMV  1024
#define HEADS 16
#define DH    64

// ---------------- scratch (device globals; total 28.25 MB) ------------------
__device__ float g_sq[BATCH * HEADS * NSEQ];                    // 0.25 MB
__device__ __half g_x16[4096 * 1024];   // 8 MB: x fp16, then attention output
__device__ __half g_w16[2048 * 1024];   // 4 MB: w_qv fp16, then w_o hi|lo planes
__device__ __half g_q16[BATCH * HEADS * NSEQ * DH];             // 8 MB [bh][n][d]
__device__ __half g_v16[BATCH * HEADS * DH * NSEQ];             // 8 MB [bh][d][n]

// ---------------- helpers ---------------------------------------------------
__device__ __forceinline__ uint32_t smem_u32(const void* p) {
    uint32_t a;
    asm("{ .reg .u64 t; cvta.to.shared.u64 t, %1; cvt.u32.u64 %0, t; }"
        : "=r"(a) : "l"(p));
    return a;
}
#define LDSM_X4(r0, r1, r2, r3, addr)                                        \
    asm volatile("ldmatrix.sync.aligned.m8n8.x4.shared.b16 {%0,%1,%2,%3}, [%4];" \
                 : "=r"(r0), "=r"(r1), "=r"(r2), "=r"(r3) : "r"(addr))
#define MMA16816H(d, a, b0, b1)                                              \
    asm volatile("mma.sync.aligned.m16n8k16.row.col.f32.f16.f16.f32 "        \
                 "{%0,%1,%2,%3}, {%4,%5,%6,%7}, {%8,%9}, {%0,%1,%2,%3};"     \
                 : "+f"((d)[0]), "+f"((d)[1]), "+f"((d)[2]), "+f"((d)[3])    \
                 : "r"((a)[0]), "r"((a)[1]), "r"((a)[2]), "r"((a)[3]),       \
                   "r"(b0), "r"(b1))
#define CP_ASYNC16(dst, src)                                                 \
    asm volatile("cp.async.cg.shared.global [%0], [%1], 16;"                 \
                 :: "r"(dst), "l"(src))
#define CP_COMMIT() asm volatile("cp.async.commit_group;" ::: "memory")
#define CP_WAIT(n)  asm volatile("cp.async.wait_group %0;" :: "n"(n) : "memory")
#define STS32(addr, v)                                                       \
    asm volatile("st.shared.u32 [%0], %1;" :: "r"(addr), "r"(v) : "memory")

union HU { __half2 h; uint32_t u; };
__device__ __forceinline__ uint32_t pack_h2(float x, float y) {
    HU t; t.h = __floats2half2_rn(x, y); return t.u;
}
__device__ __forceinline__ float ex2(float x) {
    float y; asm("ex2.approx.ftz.f32 %0, %1;" : "=f"(y) : "f"(x)); return y;
}

// ---------------------------------------------------------------------------
// convert fp32 -> fp16. which=0 -> g_x16, which=1 -> g_w16
// ---------------------------------------------------------------------------
__global__ __launch_bounds__(256) void conv16_kernel(const float* __restrict__ src,
                                                     int which, int n)
{
    int i = (blockIdx.x * 256 + threadIdx.x) * 8;
    if (i >= n) return;
    __half* dst = which ? g_w16 : g_x16;
    float4 a = *(const float4*)(src + i);
    float4 b = *(const float4*)(src + i + 4);
    uint4 hv;
    hv.x = pack_h2(a.x, a.y);  hv.y = pack_h2(a.z, a.w);
    hv.z = pack_h2(b.x, b.y);  hv.w = pack_h2(b.z, b.w);
    *(uint4*)(dst + i) = hv;
}

// ---------------------------------------------------------------------------
// split w_o fp32 -> fp16 hi plane (g_w16[0..]) + fp16 lo plane (g_w16[n..])
// ---------------------------------------------------------------------------
__global__ __launch_bounds__(256) void split_wo_kernel(const float* __restrict__ src,
                                                       int n)
{
    int i = (blockIdx.x * 256 + threadIdx.x) * 8;
    if (i >= n) return;
    float4 a = *(const float4*)(src + i);
    float4 b = *(const float4*)(src + i + 4);
    float f[8] = {a.x, a.y, a.z, a.w, b.x, b.y, b.z, b.w};
    // scalar compute, vector store (no address-taken indexing survives unroll)
    float r0 = f[0] - __half2float(__float2half(f[0]));
    float r1 = f[1] - __half2float(__float2half(f[1]));
    float r2 = f[2] - __half2float(__float2half(f[2]));
    float r3 = f[3] - __half2float(__float2half(f[3]));
    float r4 = f[4] - __half2float(__float2half(f[4]));
    float r5 = f[5] - __half2float(__float2half(f[5]));
    float r6 = f[6] - __half2float(__float2half(f[6]));
    float r7 = f[7] - __half2float(__float2half(f[7]));
    uint4 hv, lv;
    hv.x = pack_h2(f[0], f[1]);  hv.y = pack_h2(f[2], f[3]);
    hv.z = pack_h2(f[4], f[5]);  hv.w = pack_h2(f[6], f[7]);
    lv.x = pack_h2(r0, r1);      lv.y = pack_h2(r2, r3);
    lv.z = pack_h2(r4, r5);      lv.w = pack_h2(r6, r7);
    *(uint4*)(g_w16 + i)     = hv;
    *(uint4*)(g_w16 + n + i) = lv;
}

#define KDIM   1024
#define SROW   40
#define ABYTES (128 * SROW * 2)     // 10240 per operand tile

// ---------------------------------------------------------------------------
// fp16 single-pass QV GEMM (NT): qv = x16 @ w16^T, scatter q/v epilogue.
// ---------------------------------------------------------------------------
#define STAGEB16 (2 * ABYTES)
#define GEMM16_SMEM (2 * STAGEB16)  // 40960

__global__ __launch_bounds__(256, 2) void mma_gemm16()
{
    extern __shared__ char smem[];
    const uint32_t sbase = smem_u32(smem);

    const int tid  = threadIdx.x;
    const int warp = tid >> 5;
    const int lane = tid & 31;
    const int wm   = warp & 1;
    const int wn   = warp >> 1;

    const int m0 = blockIdx.y * 128;
    const int n0 = blockIdx.x * 128;

    const int lrow  = tid >> 1;
    const int lhalf = (tid & 1) * 16;
    const __half* pA = g_x16 + (size_t)(m0 + lrow) * KDIM + lhalf;
    const __half* pB = g_w16 + (size_t)(n0 + lrow) * KDIM + lhalf;
    const uint32_t so = (uint32_t)(lrow * SROW + lhalf) * 2;

    const int fr = (lane & 7) + ((lane >> 3) & 1) * 8;
    const int fc = (lane >> 4) * 8;

    float acc[4][4][4];
#pragma unroll
    for (int i = 0; i < 4; i++)
#pragma unroll
        for (int j = 0; j < 4; j++)
#pragma unroll
            for (int c = 0; c < 4; c++) acc[i][j][c] = 0.0f;

#define ISSUE16(ch) do {                                                     \
        const uint32_t st = sbase + ((ch) & 1) * STAGEB16 + so;              \
        const int ko = (ch) * 32;                                            \
        CP_ASYNC16(st,               pA + ko);                               \
        CP_ASYNC16(st + 16,          pA + ko + 8);                           \
        CP_ASYNC16(st + ABYTES,      pB + ko);                               \
        CP_ASYNC16(st + ABYTES + 16, pB + ko + 8);                           \
        CP_COMMIT();                                                         \
    } while (0)

    ISSUE16(0);

    for (int ch = 0; ch < KDIM / 32; ch++) {
        if (ch + 1 < KDIM / 32) { ISSUE16(ch + 1); CP_WAIT(1); }
        else                    { CP_WAIT(0); }
        __syncthreads();

        const char* stg = smem + (ch & 1) * STAGEB16;
        const __half* sA = (const __half*)(stg);
        const __half* sB = (const __half*)(stg + ABYTES);

#pragma unroll
        for (int ks = 0; ks < 2; ks++) {
            const int kc = ks * 16 + fc;
            uint32_t bf[2][4];
#pragma unroll
            for (int np = 0; np < 2; np++) {
                const int row = wn * 32 + np * 16 + fr;
                LDSM_X4(bf[np][0], bf[np][1], bf[np][2], bf[np][3],
                        smem_u32(sB + row * SROW + kc));
            }
#pragma unroll
            for (int mt = 0; mt < 4; mt++) {
                const int row = wm * 64 + mt * 16 + fr;
                uint32_t af[4];
                LDSM_X4(af[0], af[1], af[2], af[3],
                        smem_u32(sA + row * SROW + kc));
#pragma unroll
                for (int nt = 0; nt < 4; nt++) {
                    const int np = nt >> 1, sub = nt & 1;
                    MMA16816H(acc[mt][nt], af, bf[np][sub], bf[np][sub + 2]);
                }
            }
        }
        __syncthreads();
    }

    const int r0 = lane >> 2;
    const int c0 = (lane & 3) * 2;
#pragma unroll
    for (int mt = 0; mt < 4; mt++) {
#pragma unroll
        for (int half = 0; half < 2; half++) {
            const int m = m0 + wm * 64 + mt * 16 + r0 + half * 8;
            const int bb = m >> 11, nn = m & 2047;
#pragma unroll
            for (int nt = 0; nt < 4; nt++) {
                const int e = n0 + wn * 32 + nt * 8 + c0;
                float vx = acc[mt][nt][half * 2 + 0];
                float vy = acc[mt][nt][half * 2 + 1];
                if (e < DIMV) {
                    const int hh = e >> 6, d0 = e & 63;
                    size_t idx = (((size_t)(bb * HEADS + hh)) * NSEQ + nn) * DH + d0;
                    *(uint32_t*)(g_q16 + idx) = pack_h2(vx, vy);
                } else {
                    const int e2 = e - DIMV;
                    const int hh = e2 >> 6, d0 = e2 & 63;
                    size_t bs = ((size_t)(bb * HEADS + hh)) * DH;
                    g_v16[(bs + d0)     * NSEQ + nn] = __float2half(vx);
                    g_v16[(bs + d0 + 1) * NSEQ + nn] = __float2half(vy);
                }
            }
        }
    }
}

// ---------------------------------------------------------------------------
// fp16x2 Wo GEMM (NT): out = A16 @ (Bh + Bl)^T.  A = attention out (g_x16),
// B planes in g_w16 (hi at 0, lo at +1024*1024). grid (8, 32), occ 2.
// ---------------------------------------------------------------------------
#define STAGEBH2 (3 * ABYTES)        // 30720 per stage
#define GEMMH2_SMEM (2 * STAGEBH2)   // 61440

__global__ __launch_bounds__(256, 2) void mma_gemm_h2(float* __restrict__ C, int ldc)
{
    extern __shared__ char smem[];
    const uint32_t sbase = smem_u32(smem);

    const int tid  = threadIdx.x;
    const int warp = tid >> 5;
    const int lane = tid & 31;
    const int wm   = warp & 1;
    const int wn   = warp >> 1;

    const int m0 = blockIdx.y * 128;
    const int n0 = blockIdx.x * 128;

    const int lrow  = tid >> 1;
    const int lhalf = (tid & 1) * 16;
    const __half* pA  = g_x16 + (size_t)(m0 + lrow) * KDIM + lhalf;
    const __half* pBh = g_w16 + (size_t)(n0 + lrow) * KDIM + lhalf;
    const __half* pBl = g_w16 + 1024 * 1024 + (size_t)(n0 + lrow) * KDIM + lhalf;
    const uint32_t so = (uint32_t)(lrow * SROW + lhalf) * 2;

    const int fr = (lane & 7) + ((lane >> 3) & 1) * 8;
    const int fc = (lane >> 4) * 8;

    float acc[4][4][4];
#pragma unroll
    for (int i = 0; i < 4; i++)
#pragma unroll
        for (int j = 0; j < 4; j++)
#pragma unroll
            for (int c = 0; c < 4; c++) acc[i][j][c] = 0.0f;

#define ISSUEH2(ch) do {                                                     \
        const uint32_t st = sbase + ((ch) & 1) * STAGEBH2 + so;              \
        const int ko = (ch) * 32;                                            \
        CP_ASYNC16(st,                   pA + ko);                           \
        CP_ASYNC16(st + 16,              pA + ko + 8);                       \
        CP_ASYNC16(st + ABYTES,          pBh + ko);                          \
        CP_ASYNC16(st + ABYTES + 16,     pBh + ko + 8);                      \
        CP_ASYNC16(st + 2 * ABYTES,      pBl + ko);                          \
        CP_ASYNC16(st + 2 * ABYTES + 16, pBl + ko + 8);                      \
        CP_COMMIT();                                                         \
    } while (0)

    ISSUEH2(0);

    for (int ch = 0; ch < KDIM / 32; ch++) {
        if (ch + 1 < KDIM / 32) { ISSUEH2(ch + 1); CP_WAIT(1); }
        else                    { CP_WAIT(0); }
        __syncthreads();

        const char* stg = smem + (ch & 1) * STAGEBH2;
        const __half* sA  = (const __half*)(stg);
        const __half* sBh = (const __half*)(stg + ABYTES);
        const __half* sBl = (const __half*)(stg + 2 * ABYTES);

#pragma unroll
        for (int ks = 0; ks < 2; ks++) {
            const int kc = ks * 16 + fc;
            uint32_t bh[2][4], bl[2][4];
#pragma unroll
            for (int np = 0; np < 2; np++) {
                const int row = wn * 32 + np * 16 + fr;
                LDSM_X4(bh[np][0], bh[np][1], bh[np][2], bh[np][3],
                        smem_u32(sBh + row * SROW + kc));
                LDSM_X4(bl[np][0], bl[np][1], bl[np][2], bl[np][3],
                        smem_u32(sBl + row * SROW + kc));
            }
#pragma unroll
            for (int mt = 0; mt < 4; mt++) {
                const int row = wm * 64 + mt * 16 + fr;
                uint32_t af[4];
                LDSM_X4(af[0], af[1], af[2], af[3],
                        smem_u32(sA + row * SROW + kc));
#pragma unroll
                for (int nt = 0; nt < 4; nt++) {
                    const int np = nt >> 1, sub = nt & 1;
                    MMA16816H(acc[mt][nt], af, bh[np][sub], bh[np][sub + 2]);
                    MMA16816H(acc[mt][nt], af, bl[np][sub], bl[np][sub + 2]);
                }
            }
        }
        __syncthreads();
    }

    const int r0 = lane >> 2;
    const int c0 = (lane & 3) * 2;
#pragma unroll
    for (int mt = 0; mt < 4; mt++) {
#pragma unroll
        for (int half = 0; half < 2; half++) {
            const int m = m0 + wm * 64 + mt * 16 + r0 + half * 8;
#pragma unroll
            for (int nt = 0; nt < 4; nt++) {
                const int e = n0 + wn * 32 + nt * 8 + c0;
                float2 v;
                v.x = acc[mt][nt][half * 2 + 0];
                v.y = acc[mt][nt][half * 2 + 1];
                *(float2*)(C + (size_t)m * ldc + e) = v;
            }
        }
    }
}

// ---------------------------------------------------------------------------
// ||q||^2 per row from the fp16-rounded q
// ---------------------------------------------------------------------------
__global__ __launch_bounds__(256) void sq_kernel()
{
    int row = blockIdx.x * blockDim.x + threadIdx.x;
    if (row >= BATCH * HEADS * NSEQ) return;
    const __half2* p = (const __half2*)(g_q16 + (size_t)row * DH);
    float s = 0.0f;
#pragma unroll
    for (int i = 0; i < 32; i++) {
        float2 f = __half22float2(p[i]);
        s += f.x * f.x + f.y * f.y;
    }
    g_sq[row] = s;
}

// ---------------------------------------------------------------------------
// fp16 mma.sync L2 attention. Epilogue writes plain fp16 into g_x16.
// ---------------------------------------------------------------------------
#define A_SQ   0
#define A_ST0  18432
#define A_STSZ 18688
#define A_K    0
#define A_V    9216
#define A_SQS  18432
#define A_PH   55808
#define A_L2D  74240
#define ATT_SMEM 75264

__global__ __launch_bounds__(256, 2) void mma_attn()
{
    extern __shared__ char sm[];
    const uint32_t sb = smem_u32(sm);
    const int tid  = threadIdx.x;
    const int warp = tid >> 5;
    const int lane = tid & 31;
    const int wm   = warp & 3;
    const int wn   = warp >> 2;
    const int qb = blockIdx.x, h = blockIdx.y, b = blockIdx.z;
    const int bh = b * HEADS + h;

    const __half* Qg = g_q16 + (size_t)bh * NSEQ * DH;
    const __half* Vg = g_v16 + (size_t)bh * DH * NSEQ;
    const float* sqg = g_sq + (size_t)bh * NSEQ;

    const int fr = (lane & 7) + ((lane >> 3) & 1) * 8;
    const int fc = (lane >> 4) * 8;
    const int r4 = lane >> 2;
    const int c2 = (lane & 3) * 2;

    const float C = 0.18033688011112042f;  // log2(e)/8

    float sqnC[2][2];
#pragma unroll
    for (int mt = 0; mt < 2; mt++) {
        sqnC[mt][0] = sqg[qb * 128 + wm * 32 + mt * 16 + r4]     * C;
        sqnC[mt][1] = sqg[qb * 128 + wm * 32 + mt * 16 + r4 + 8] * C;
    }

    for (int s = tid; s < 128 * 8; s += 256) {
        int row = s >> 3, seg = s & 7;
        CP_ASYNC16(sb + A_SQ + row * 144 + seg * 16,
                   Qg + (size_t)(qb * 128 + row) * DH + seg * 8);
    }

    auto issue_tile = [&](int t) {
        const uint32_t stb = sb + A_ST0 + (t & 1) * A_STSZ;
        for (int s = tid; s < 64 * 8; s += 256) {
            int row = s >> 3, seg = s & 7;
            CP_ASYNC16(stb + A_K + row * 144 + seg * 16,
                       Qg + (size_t)(t * 64 + row) * DH + seg * 8);
            CP_ASYNC16(stb + A_V + row * 144 + seg * 16,
                       Vg + (size_t)row * NSEQ + t * 64 + seg * 8);
        }
        if (tid < 16)
            CP_ASYNC16(stb + A_SQS + tid * 16, sqg + t * 64 + tid * 4);
        CP_COMMIT();
    };

    issue_tile(0);

    float acc[2][4][4];
#pragma unroll
    for (int i = 0; i < 2; i++)
#pragma unroll
        for (int j = 0; j < 4; j++)
#pragma unroll
            for (int c = 0; c < 4; c++) acc[i][j][c] = 0.0f;
    float lacc[2][2] = {{0.f, 0.f}, {0.f, 0.f}};

    for (int t = 0; t < NSEQ / 64; t++) {
        if (t + 1 < NSEQ / 64) { issue_tile(t + 1); CP_WAIT(1); }
        else                   { CP_WAIT(0); }
        __syncthreads();

        const uint32_t kb = sb + A_ST0 + (t & 1) * A_STSZ;
        const float* sqs = (const float*)(sm + A_ST0 + (t & 1) * A_STSZ + A_SQS);

        float S[2][4][4];
#pragma unroll
        for (int i = 0; i < 2; i++)
#pragma unroll
            for (int j = 0; j < 4; j++)
#pragma unroll
                for (int c = 0; c < 4; c++) S[i][j][c] = 0.0f;

#pragma unroll
        for (int kc = 0; kc < 4; kc++) {
            const int colb = (kc * 16 + fc) * 2;
            uint32_t kf[2][4];
#pragma unroll
            for (int np = 0; np < 2; np++) {
                const int row = wn * 32 + np * 16 + fr;
                LDSM_X4(kf[np][0], kf[np][1], kf[np][2], kf[np][3],
                        kb + A_K + row * 144 + colb);
            }
#pragma unroll
            for (int mt = 0; mt < 2; mt++) {
                const int arow = wm * 32 + mt * 16 + fr;
                uint32_t ah[4];
                LDSM_X4(ah[0], ah[1], ah[2], ah[3], sb + A_SQ + arow * 144 + colb);
#pragma unroll
                for (int nt = 0; nt < 4; nt++) {
                    const int np = nt >> 1, sub = nt & 1;
                    MMA16816H(S[mt][nt], ah, kf[np][sub], kf[np][sub + 2]);
                }
            }
        }

#pragma unroll
        for (int mt = 0; mt < 2; mt++) {
#pragma unroll
            for (int nt = 0; nt < 4; nt++) {
                const int col = wn * 32 + nt * 8 + c2;
                const float sqm0 = sqs[col], sqm1 = sqs[col + 1];
                float p0 = ex2(fmaf(fmaf(2.f, S[mt][nt][0], -sqm0), C, -sqnC[mt][0]));
                float p1 = ex2(fmaf(fmaf(2.f, S[mt][nt][1], -sqm1), C, -sqnC[mt][0]));
                float p2 = ex2(fmaf(fmaf(2.f, S[mt][nt][2], -sqm0), C, -sqnC[mt][1]));
                float p3 = ex2(fmaf(fmaf(2.f, S[mt][nt][3], -sqm1), C, -sqnC[mt][1]));
                HU u01; u01.h = __floats2half2_rn(p0, p1);
                HU u23; u23.h = __floats2half2_rn(p2, p3);
                float2 f01 = __half22float2(u01.h);
                float2 f23 = __half22float2(u23.h);
                lacc[mt][0] += f01.x + f01.y;
                lacc[mt][1] += f23.x + f23.y;
                const int row = wm * 32 + mt * 16 + r4;
                const uint32_t cb = col * 2;
                STS32(sb + A_PH + row * 144 + cb,       u01.u);
                STS32(sb + A_PH + (row + 8) * 144 + cb, u23.u);
            }
        }
        __syncthreads();

#pragma unroll
        for (int kc = 0; kc < 4; kc++) {
            const int colb = (kc * 16 + fc) * 2;
            uint32_t vf[2][4];
#pragma unroll
            for (int np = 0; np < 2; np++) {
                const int row = wn * 32 + np * 16 + fr;
                LDSM_X4(vf[np][0], vf[np][1], vf[np][2], vf[np][3],
                        kb + A_V + row * 144 + colb);
            }
#pragma unroll
            for (int mt = 0; mt < 2; mt++) {
                const int arow = wm * 32 + mt * 16 + fr;
                uint32_t ph[4];
                LDSM_X4(ph[0], ph[1], ph[2], ph[3], sb + A_PH + arow * 144 + colb);
#pragma unroll
                for (int nt = 0; nt < 4; nt++) {
                    const int np = nt >> 1, sub = nt & 1;
                    MMA16816H(acc[mt][nt], ph, vf[np][sub], vf[np][sub + 2]);
                }
            }
        }
        __syncthreads();
    }

    float* l2d = (float*)(sm + A_L2D);
#pragma unroll
    for (int mt = 0; mt < 2; mt++)
#pragma unroll
        for (int hf = 0; hf < 2; hf++) {
            float l = lacc[mt][hf];
            l += __shfl_xor_sync(0xffffffffu, l, 1);
            l += __shfl_xor_sync(0xffffffffu, l, 2);
            if ((lane & 3) == 0)
                l2d[wn * 128 + wm * 32 + mt * 16 + hf * 8 + r4] = l;
        }
    __syncthreads();

    // epilogue: normalize, write fp16 into g_x16 (A of Wo gemm)
#pragma unroll
    for (int mt = 0; mt < 2; mt++) {
#pragma unroll
        for (int hf = 0; hf < 2; hf++) {
            const int row = wm * 32 + mt * 16 + hf * 8 + r4;
            const float linv = 1.0f / (l2d[row] + l2d[128 + row]);
            const int n = qb * 128 + row;
#pragma unroll
            for (int nt = 0; nt < 4; nt++) {
                const int dcol = h * DH + wn * 32 + nt * 8 + c2;
                const float vx = acc[mt][nt][hf * 2 + 0] * linv;
                const float vy = acc[mt][nt][hf * 2 + 1] * linv;
                size_t idx = ((size_t)b * NSEQ + n) * DIMV + dcol;
                *(uint32_t*)(g_x16 + idx) = pack_h2(vx, vy);
            }
        }
    }
}

// ---------------------------------------------------------------------------

extern "C" void kernel_launch(void* const* d_in, const int* in_sizes, int n_in,
                              void* d_out, int out_size)
{
    const float* x    = (const float*)d_in[0];   // [2,2048,1024]
    const float* w_qv = (const float*)d_in[1];   // [2048,1024]
    const float* w_o  = (const float*)d_in[2];   // [1024,1024]
    float* out = (float*)d_out;                  // [2,2048,1024]

    cudaFuncSetAttribute(mma_gemm16, cudaFuncAttributeMaxDynamicSharedMemorySize,
                         GEMM16_SMEM);
    cudaFuncSetAttribute(mma_gemm_h2, cudaFuncAttributeMaxDynamicSharedMemorySize,
                         GEMMH2_SMEM);
    cudaFuncSetAttribute(mma_attn, cudaFuncAttributeMaxDynamicSharedMemorySize,
                         ATT_SMEM);

    // 1) convert x, w_qv to fp16
    conv16_kernel<<<4096 * 1024 / 8 / 256, 256>>>(x, 0, 4096 * 1024);
    conv16_kernel<<<2048 * 1024 / 8 / 256, 256>>>(w_qv, 1, 2048 * 1024);

    // 2) fp16 QV projection -> q (row-major) / v (transposed)
    mma_gemm16<<<dim3(16, 32), 256, GEMM16_SMEM>>>();

    // 3) split w_o -> fp16 hi/lo planes (overwrites w_qv copy); ||q||^2
    split_wo_kernel<<<1024 * 1024 / 8 / 256, 256>>>(w_o, 1024 * 1024);
    sq_kernel<<<(BATCH * HEADS * NSEQ) / 256, 256>>>();

    // 4) fp16 tensor-core attention -> fp16 output into g_x16
    mma_attn<<<dim3(NSEQ / 128, HEADS, BATCH), 256, ATT_SMEM>>>();

    // 5) fp16x2 Wo projection -> out
    mma_gemm_h2<<<dim3(8, 32), 256, GEMMH2_SMEM>>>(out, 1024);
}